// round 12
// baseline (speedup 1.0000x reference)
#include <cuda_runtime.h>
#include <cuda_bf16.h>
#include <cstdint>

// ---------------- problem dims ----------------
#define B_   2
#define T_   2048
#define HID  2048
#define NH   6
#define DK   256
#define DV   512
#define KD   1536
#define VD   3072
#define BT   4096
#define CK   4

// fused projection layout: [q(1536) | k(1536) | v(3072) | g(3072)]
#define PST  9216
#define QOFF 0
#define KOFF 1536
#define VOFF 3072
#define GOFF 6144

typedef unsigned long long ull;

// ---------------- scratch (device globals; no allocs allowed) ----------------
__device__ float d_P[(size_t)BT * PST];
__device__ float d_Qc[BT * KD];
__device__ float d_Kc[BT * KD];
__device__ float d_Vc[(size_t)BT * VD];
__device__ float d_EG[BT * NH];
__device__ float d_Beta[BT * NH];
__device__ float d_O[(size_t)BT * VD];

// operand buffers: bf16-hi + fp8 hi/lo
__device__ __nv_bfloat16 d_Hh[(size_t)BT * HID];
__device__ uint8_t d_H8h[(size_t)BT * HID];
__device__ uint8_t d_H8l[(size_t)BT * HID];
__device__ __nv_bfloat16 d_Wbh[(size_t)HID * PST];   // [Wq|Wk|Wv|Wg] bf16 hi, [K,N]
__device__ uint8_t d_W8h[(size_t)PST * HID];         // fp8 hi, transposed [N,K]
__device__ uint8_t d_W8l[(size_t)PST * HID];         // fp8 lo(x512), [N,K]
__device__ __nv_bfloat16 d_Woh[(size_t)VD * HID];    // Wo bf16 hi [K=VD, N=HID]
__device__ uint8_t d_Wo8h[(size_t)HID * VD];         // Wo fp8 hi [N=HID, K=VD]
__device__ uint8_t d_Wo8l[(size_t)HID * VD];
__device__ __nv_bfloat16 d_Gh[(size_t)BT * VD];
__device__ uint8_t d_G8h[(size_t)BT * VD];
__device__ uint8_t d_G8l[(size_t)BT * VD];

// ---------------- packed f32x2 helpers (recurrence) ----------------
__device__ __forceinline__ ull fma2(ull a, ull b, ull c) {
    ull d;
    asm("fma.rn.f32x2 %0, %1, %2, %3;" : "=l"(d) : "l"(a), "l"(b), "l"(c));
    return d;
}
__device__ __forceinline__ ull mul2(ull a, ull b) {
    ull d;
    asm("mul.rn.f32x2 %0, %1, %2;" : "=l"(d) : "l"(a), "l"(b));
    return d;
}
__device__ __forceinline__ ull add2(ull a, ull b) {
    ull d;
    asm("add.rn.f32x2 %0, %1, %2;" : "=l"(d) : "l"(a), "l"(b));
    return d;
}
__device__ __forceinline__ ull pack2(float lo, float hi) {
    ull d;
    asm("mov.b64 %0, {%1, %2};" : "=l"(d) : "f"(lo), "f"(hi));
    return d;
}
__device__ __forceinline__ void unpack2(ull v, float& lo, float& hi) {
    asm("mov.b64 {%0, %1}, %2;" : "=f"(lo), "=f"(hi) : "l"(v));
}
__device__ __forceinline__ float sigm(float x) { return 1.0f / (1.0f + __expf(-x)); }

// ---------------- conversion helpers ----------------
__device__ __forceinline__ uint32_t smem_u32(const void* p) {
    uint32_t a;
    asm("{ .reg .u64 t; cvta.to.shared.u64 t, %1; cvt.u32.u64 %0, t; }" : "=r"(a) : "l"(p));
    return a;
}
__device__ __forceinline__ uint32_t pkbf(float x, float y) {
    uint32_t r;
    asm("cvt.rn.bf16x2.f32 %0, %1, %2;" : "=r"(r) : "f"(y), "f"(x));
    return r;
}
__device__ __forceinline__ float bfhi(float x) {
    uint32_t r;
    asm("cvt.rn.bf16x2.f32 %0, %1, %1;" : "=r"(r) : "f"(x));
    return __uint_as_float(r << 16);
}
// pack 4 floats into 4 e4m3 bytes (x0 -> byte0)
__device__ __forceinline__ uint32_t pk8x4(float x0, float x1, float x2, float x3) {
    uint32_t r;
    asm("{\n\t.reg .b16 t0, t1;\n\t"
        "cvt.rn.satfinite.e4m3x2.f32 t0, %2, %1;\n\t"
        "cvt.rn.satfinite.e4m3x2.f32 t1, %4, %3;\n\t"
        "mov.b32 %0, {t0, t1};\n\t}"
        : "=r"(r) : "f"(x0), "f"(x1), "f"(x2), "f"(x3));
    return r;
}
__device__ __forceinline__ uint8_t f2e4(float x) {
    uint16_t t;
    asm("cvt.rn.satfinite.e4m3x2.f32 %0, %1, %1;" : "=h"(t) : "f"(x));
    return (uint8_t)(t & 0xff);
}

// ---------------- mma machinery ----------------
__device__ __forceinline__ void ldsm_x4(uint32_t* r, uint32_t a) {
    asm volatile("ldmatrix.sync.aligned.m8n8.x4.shared.b16 {%0,%1,%2,%3}, [%4];"
                 : "=r"(r[0]), "=r"(r[1]), "=r"(r[2]), "=r"(r[3]) : "r"(a));
}
__device__ __forceinline__ void ldsm_x4_t(uint32_t* r, uint32_t a) {
    asm volatile("ldmatrix.sync.aligned.m8n8.x4.trans.shared.b16 {%0,%1,%2,%3}, [%4];"
                 : "=r"(r[0]), "=r"(r[1]), "=r"(r[2]), "=r"(r[3]) : "r"(a));
}
__device__ __forceinline__ void mma_bf16(float* d, const uint32_t* a, const uint32_t* b) {
    asm volatile(
        "mma.sync.aligned.m16n8k16.row.col.f32.bf16.bf16.f32 "
        "{%0,%1,%2,%3}, {%4,%5,%6,%7}, {%8,%9}, {%0,%1,%2,%3};"
        : "+f"(d[0]), "+f"(d[1]), "+f"(d[2]), "+f"(d[3])
        : "r"(a[0]), "r"(a[1]), "r"(a[2]), "r"(a[3]), "r"(b[0]), "r"(b[1]));
}
__device__ __forceinline__ void mma_e4m3(float* d, const uint32_t* a, uint32_t b0, uint32_t b1) {
    asm volatile(
        "mma.sync.aligned.m16n8k32.row.col.f32.e4m3.e4m3.f32 "
        "{%0,%1,%2,%3}, {%4,%5,%6,%7}, {%8,%9}, {%0,%1,%2,%3};"
        : "+f"(d[0]), "+f"(d[1]), "+f"(d[2]), "+f"(d[3])
        : "r"(a[0]), "r"(a[1]), "r"(a[2]), "r"(a[3]), "r"(b0), "r"(b1));
}
__device__ __forceinline__ void cpa16(uint32_t dst, const void* src) {
    asm volatile("cp.async.cg.shared.global [%0], [%1], 16;" :: "r"(dst), "l"(src));
}
__device__ __forceinline__ void cpa4(uint32_t dst, const void* src) {
    asm volatile("cp.async.ca.shared.global [%0], [%1], 4;" :: "r"(dst), "l"(src));
}
#define CP_COMMIT() asm volatile("cp.async.commit_group;" ::: "memory")
#define CP_WAIT1()  asm volatile("cp.async.wait_group 1;" ::: "memory")
#define CP_WAIT2()  asm volatile("cp.async.wait_group 2;" ::: "memory")

// tiles: 128(M) x 64(N), BK=32, 3 stages
#define BM 128
#define BN 64
#define BKf 32
#define STAGES 3
#define A_STR 80        // bf16 A row: 64B + 16 pad
#define B_STR 144       // bf16 B row: 128B + 16 pad
#define A8_STR 48       // fp8 row: 32B + 16 pad
#define AT_BYTES (128 * A_STR)     // 10240
#define BT_BYTES (32 * B_STR)      // 4608
#define A8T_BYTES (128 * A8_STR)   // 6144
#define B8T_BYTES (64 * A8_STR)    // 3072
#define OFF_A 0
#define OFF_B AT_BYTES
#define OFF_A8H (AT_BYTES + BT_BYTES)
#define OFF_A8L (OFF_A8H + A8T_BYTES)
#define OFF_B8H (OFF_A8L + A8T_BYTES)
#define OFF_B8L (OFF_B8H + B8T_BYTES)
#define STAGE_BYTES (OFF_B8L + B8T_BYTES)   // 33280
#define SMEM_GB (STAGES * STAGE_BYTES)      // 99840

__device__ __forceinline__ void g_issue(uint32_t st,
                                        const __nv_bfloat16* __restrict__ Ah,
                                        const uint8_t* __restrict__ A8h,
                                        const uint8_t* __restrict__ A8l,
                                        const __nv_bfloat16* __restrict__ Bh,
                                        const uint8_t* __restrict__ B8h,
                                        const uint8_t* __restrict__ B8l,
                                        int m0, int n0, int kt, int K, int ldb, int tid) {
    // bf16 A: 128 rows x 64B
#pragma unroll
    for (int half = 0; half < 2; half++) {
        int r = (tid >> 2) + half * 64;
        int ke = (tid & 3) * 8;
        cpa16(st + OFF_A + r * A_STR + ke * 2, Ah + (size_t)(m0 + r) * K + kt * BKf + ke);
    }
    // bf16 B: 32 rows x 128B
    {
        int r = tid >> 3;
        int ke = (tid & 7) * 8;
        cpa16(st + OFF_B + r * B_STR + ke * 2, Bh + (size_t)(kt * BKf + r) * ldb + n0 + ke);
    }
    // fp8 A hi/lo: 128 rows x 32B
    {
        int r = tid >> 1;
        int kb = (tid & 1) * 16;
        const size_t ga = (size_t)(m0 + r) * K + kt * BKf + kb;
        cpa16(st + OFF_A8H + r * A8_STR + kb, A8h + ga);
        cpa16(st + OFF_A8L + r * A8_STR + kb, A8l + ga);
    }
    // fp8 B hi/lo (transposed [N,K], row stride K): 64 n-rows x 32B
    if (tid < 128) {
        int r = tid >> 1;
        int kb = (tid & 1) * 16;
        const size_t gb = (size_t)(n0 + r) * K + kt * BKf + kb;
        cpa16(st + OFF_B8H + r * A8_STR + kb, B8h + gb);
        cpa16(st + OFF_B8L + r * A8_STR + kb, B8l + gb);
    }
}

__device__ __forceinline__ void g_compute(uint32_t st, int wid, int lane,
                                          float (*acc)[4][4], float (*acc2)[4][4]) {
    const int wm = (wid & 3) * 32, wn = (wid >> 2) * 32;
    const int arow = lane & 15;
    const int acg = (lane >> 4) * 8;
    const int brow = (lane & 7) + ((lane >> 3) & 1) * 8;
    const int bcg = (lane >> 4) * 8;

    // ---- main bf16 term ----
#pragma unroll
    for (int ks = 0; ks < BKf; ks += 16) {
        uint32_t ah[2][4], bh[2][4];
#pragma unroll
        for (int mt = 0; mt < 2; mt++)
            ldsm_x4(ah[mt], st + OFF_A + (wm + mt * 16 + arow) * A_STR + (ks + acg) * 2);
#pragma unroll
        for (int nt = 0; nt < 2; nt++)
            ldsm_x4_t(bh[nt], st + OFF_B + (ks + brow) * B_STR + (wn + nt * 16 + bcg) * 2);
#pragma unroll
        for (int mt = 0; mt < 2; mt++)
#pragma unroll
            for (int j = 0; j < 4; j++)
                mma_bf16(acc[mt][j], ah[mt], &bh[j >> 1][(j & 1) * 2]);
    }

    // ---- fp8 correction terms (k32) ----
    uint32_t a8h[2][4], a8l[2][4], b8h[2][4], b8l[2][4];
#pragma unroll
    for (int mt = 0; mt < 2; mt++) {
        uint32_t ad = st + OFF_A8H + (wm + mt * 16 + (lane & 15)) * A8_STR + (lane >> 4) * 16;
        ldsm_x4(a8h[mt], ad);
        ldsm_x4(a8l[mt], ad + (OFF_A8L - OFF_A8H));
    }
#pragma unroll
    for (int p = 0; p < 2; p++) {
        uint32_t bd = st + OFF_B8H + (wn + p * 16 + (lane & 15)) * A8_STR + (lane >> 4) * 16;
        ldsm_x4(b8h[p], bd);
        ldsm_x4(b8l[p], bd + (OFF_B8L - OFF_B8H));
    }
#pragma unroll
    for (int mt = 0; mt < 2; mt++)
#pragma unroll
        for (int p = 0; p < 2; p++) {
            mma_e4m3(acc2[mt][2 * p],     a8h[mt], b8l[p][0], b8l[p][2]);
            mma_e4m3(acc2[mt][2 * p],     a8l[mt], b8h[p][0], b8h[p][2]);
            mma_e4m3(acc2[mt][2 * p + 1], a8h[mt], b8l[p][1], b8l[p][3]);
            mma_e4m3(acc2[mt][2 * p + 1], a8l[mt], b8h[p][1], b8h[p][3]);
        }
}

// C[M,*] = A[M,K] @ B[K,*]; bf16-hi main + fp8 cross corrections (x512 scaled)
__global__ __launch_bounds__(256, 1) void gemm_bf8(const __nv_bfloat16* __restrict__ Ah,
                                                   const uint8_t* __restrict__ A8h,
                                                   const uint8_t* __restrict__ A8l,
                                                   const __nv_bfloat16* __restrict__ Bh,
                                                   const uint8_t* __restrict__ B8h,
                                                   const uint8_t* __restrict__ B8l,
                                                   float* __restrict__ C,
                                                   int M, int K, int ldb, int ldc) {
    extern __shared__ char smem[];
    const uint32_t sb = smem_u32(smem);
    const int tid = threadIdx.x, lane = tid & 31, wid = tid >> 5;
    const int m0 = blockIdx.y * BM, n0 = blockIdx.x * BN;
    const int NT = K / BKf;

    float acc[2][4][4], acc2[2][4][4];
#pragma unroll
    for (int mt = 0; mt < 2; mt++)
#pragma unroll
        for (int j = 0; j < 4; j++)
#pragma unroll
            for (int p = 0; p < 4; p++) { acc[mt][j][p] = 0.0f; acc2[mt][j][p] = 0.0f; }

    g_issue(sb, Ah, A8h, A8l, Bh, B8h, B8l, m0, n0, 0, K, ldb, tid);
    CP_COMMIT();
    g_issue(sb + STAGE_BYTES, Ah, A8h, A8l, Bh, B8h, B8l, m0, n0, 1, K, ldb, tid);
    CP_COMMIT();

    for (int kt = 0; kt < NT; kt++) {
        CP_WAIT1();
        __syncthreads();
        const int pf = kt + 2;
        if (pf < NT)
            g_issue(sb + (pf % STAGES) * STAGE_BYTES, Ah, A8h, A8l, Bh, B8h, B8l,
                    m0, n0, pf, K, ldb, tid);
        CP_COMMIT();
        g_compute(sb + (kt % STAGES) * STAGE_BYTES, wid, lane, acc, acc2);
    }

    const int wm = (wid & 3) * 32, wn = (wid >> 2) * 32;
    const int g = lane >> 2, t = lane & 3;
    const float inv512 = 1.0f / 512.0f;
#pragma unroll
    for (int mt = 0; mt < 2; mt++)
#pragma unroll
        for (int j = 0; j < 4; j++) {
            float* p = C + (size_t)(m0 + wm + mt * 16 + g) * ldc + n0 + wn + j * 8 + t * 2;
            float2 c0 = make_float2(acc[mt][j][0] + acc2[mt][j][0] * inv512,
                                    acc[mt][j][1] + acc2[mt][j][1] * inv512);
            float2 c1 = make_float2(acc[mt][j][2] + acc2[mt][j][2] * inv512,
                                    acc[mt][j][3] + acc2[mt][j][3] * inv512);
            *(float2*)p = c0;
            *(float2*)(p + (size_t)8 * ldc) = c1;
        }
}

// ---------------- A-side split: bf16 hi + fp8 hi + fp8 lo(x512), contiguous ----------------
__global__ __launch_bounds__(256) void splitA_kernel(const float4* __restrict__ src,
                                                     uint2* __restrict__ hh,
                                                     uint32_t* __restrict__ a8h,
                                                     uint32_t* __restrict__ a8l, int n4) {
    int i = blockIdx.x * 256 + threadIdx.x;
    if (i >= n4) return;
    float4 v = src[i];
    uint32_t h01 = pkbf(v.x, v.y), h23 = pkbf(v.z, v.w);
    float hx = __uint_as_float(h01 << 16);
    float hy = __uint_as_float(h01 & 0xffff0000u);
    float hz = __uint_as_float(h23 << 16);
    float hw = __uint_as_float(h23 & 0xffff0000u);
    hh[i] = make_uint2(h01, h23);
    a8h[i] = pk8x4(v.x, v.y, v.z, v.w);
    a8l[i] = pk8x4((v.x - hx) * 512.0f, (v.y - hy) * 512.0f,
                   (v.z - hz) * 512.0f, (v.w - hw) * 512.0f);
}

// ---------------- B-side bf16-hi split into strided (concatenated) dest ----------------
__global__ __launch_bounds__(256) void splitWh_s(const float4* __restrict__ src,
                                                 __nv_bfloat16* __restrict__ dh,
                                                 int n4, int ncols4, int colOff) {
    int i = blockIdx.x * 256 + threadIdx.x;
    if (i >= n4) return;
    int row = i / ncols4;
    int c4 = i - row * ncols4;
    float4 v = src[i];
    *(uint2*)(dh + (size_t)row * PST + colOff + c4 * 4) =
        make_uint2(pkbf(v.x, v.y), pkbf(v.z, v.w));
}
// contiguous bf16-hi split (Wo)
__global__ __launch_bounds__(256) void splitWh_c(const float4* __restrict__ src,
                                                 uint2* __restrict__ dh, int n4) {
    int i = blockIdx.x * 256 + threadIdx.x;
    if (i >= n4) return;
    float4 v = src[i];
    dh[i] = make_uint2(pkbf(v.x, v.y), pkbf(v.z, v.w));
}

// ---------------- B-side fp8 hi/lo, TRANSPOSED to [N,K] (concat via rowOff) ----------------
__global__ __launch_bounds__(256) void transW8_kernel(const float* __restrict__ W,
                                                      uint32_t* __restrict__ B8h,
                                                      uint32_t* __restrict__ B8l,
                                                      int K, int N, int rowOff) {
    __shared__ float s[32][33];
    const int k0 = blockIdx.y * 32, n0 = blockIdx.x * 32;
    const int t = threadIdx.x;
    const int r = t >> 3, c4 = (t & 7) * 4;
    float4 v = *(const float4*)(W + (size_t)(k0 + r) * N + n0 + c4);
    s[r][c4] = v.x; s[r][c4 + 1] = v.y; s[r][c4 + 2] = v.z; s[r][c4 + 3] = v.w;
    __syncthreads();
    const int rn = t >> 3, k4 = (t & 7) * 4;
    float x0 = s[k4][rn], x1 = s[k4 + 1][rn], x2 = s[k4 + 2][rn], x3 = s[k4 + 3][rn];
    float l0 = (x0 - bfhi(x0)) * 512.0f;
    float l1 = (x1 - bfhi(x1)) * 512.0f;
    float l2 = (x2 - bfhi(x2)) * 512.0f;
    float l3 = (x3 - bfhi(x3)) * 512.0f;
    size_t o = ((size_t)(rowOff + n0 + rn) * K + k0 + k4) >> 2;
    B8h[o] = pk8x4(x0, x1, x2, x3);
    B8l[o] = pk8x4(l0, l1, l2, l3);
}

// ---------------- gate projections: g -> exp(g), beta ----------------
__global__ __launch_bounds__(256) void gate_kernel(const float* __restrict__ H,
                                                   const float* __restrict__ Wa,
                                                   const float* __restrict__ Wb,
                                                   const float* __restrict__ A_log,
                                                   const float* __restrict__ dt_bias) {
    __shared__ float hrow[HID];
    const int bt = blockIdx.x;
    const int tid = threadIdx.x;
    for (int i = tid; i < HID; i += 256) hrow[i] = H[(size_t)bt * HID + i];
    __syncthreads();
    const int w = tid >> 5, lane = tid & 31;
    for (int d = w; d < 12; d += 8) {
        const int head = d % 6;
        const float* Wc = (d < 6) ? Wa : Wb;
        float s = 0.0f;
        for (int i = lane; i < HID; i += 32) s += hrow[i] * Wc[i * NH + head];
#pragma unroll
        for (int m = 16; m > 0; m >>= 1) s += __shfl_xor_sync(0xffffffffu, s, m);
        if (lane == 0) {
            if (d < 6) {
                float x = s + dt_bias[head];
                float sp = (x > 20.0f) ? x : log1pf(expf(x));
                float g = -expf(A_log[head]) * sp;
                d_EG[bt * NH + head] = expf(g);
            } else {
                d_Beta[bt * NH + head] = sigm(s);
            }
        }
    }
}

// ---------------- causal depthwise conv + silu + per-head l2norm (q/k) ----------------
__global__ __launch_bounds__(256) void convqk_kernel(const float* __restrict__ P,
                                                     const float* __restrict__ W,
                                                     float* __restrict__ out,
                                                     float scale, int colOff) {
    const int bt = blockIdx.x;
    const int h = blockIdx.y;
    const int c = threadIdx.x;
    const int ch = h * DK + c;
    const int t = bt & (T_ - 1);
    float acc = 0.0f;
#pragma unroll
    for (int j = 0; j < CK; j++) {
        int tt = t - (CK - 1) + j;
        if (tt >= 0) acc += P[(size_t)(bt - (CK - 1) + j) * PST + colOff + ch] * W[ch * CK + j];
    }
    float y = acc * sigm(acc);

    __shared__ float red[8];
    float ss = y * y;
#pragma unroll
    for (int m = 16; m > 0; m >>= 1) ss += __shfl_xor_sync(0xffffffffu, ss, m);
    if ((c & 31) == 0) red[c >> 5] = ss;
    __syncthreads();
    float tot = 0.0f;
#pragma unroll
    for (int i = 0; i < 8; i++) tot += red[i];
    float r = rsqrtf(tot + 1e-6f);
    out[(size_t)bt * KD + ch] = y * r * scale;
}

// ---------------- causal depthwise conv + silu (v) ----------------
__global__ __launch_bounds__(256) void convv_kernel(const float* __restrict__ P,
                                                    const float* __restrict__ W) {
    const int bt = blockIdx.x;
    const int ch = blockIdx.y * 256 + threadIdx.x;
    const int t = bt & (T_ - 1);
    float acc = 0.0f;
#pragma unroll
    for (int j = 0; j < CK; j++) {
        int tt = t - (CK - 1) + j;
        if (tt >= 0) acc += P[(size_t)(bt - (CK - 1) + j) * PST + VOFF + ch] * W[ch * CK + j];
    }
    d_Vc[(size_t)bt * VD + ch] = acc * sigm(acc);
}

// ---------------- gated delta-rule recurrence (cp.async smem ring, 4-way ILP) ----------------
#define RSLOT 640
__global__ __launch_bounds__(256, 1) void recur_kernel() {
    __shared__ __align__(16) float ring[4][RSLOT];
    const int bid = blockIdx.x;
    const int chunk = bid & 7;
    const int bh = bid >> 3;
    const int b = bh / NH, h = bh % NH;
    const int tid = threadIdx.x;
    const int warp = tid >> 5, lane = tid & 31;
    const int rg = lane >> 1, cg = lane & 1;
    const int bt0 = b * T_;

    const float* Kb = d_Kc + h * DK;
    const float* Qb = d_Qc + h * DK;
    const float* Vb = d_Vc + h * DV + chunk * 64;
    float* Ob = d_O + h * DV + chunk * 64 + warp * 8 + cg * 4;

    ull S[16][2];
#pragma unroll
    for (int r = 0; r < 16; r++) { S[r][0] = 0ull; S[r][1] = 0ull; }

    auto issue = [&](int slot, int t) {
        const int bt = bt0 + t;
        uint32_t sd = smem_u32(&ring[slot][0]);
        if (tid < 64) {
            cpa16(sd + tid * 16, Kb + (size_t)bt * KD + tid * 4);
        } else if (tid < 128) {
            cpa16(sd + 1024 + (tid - 64) * 16, Qb + (size_t)bt * KD + (tid - 64) * 4);
        } else if (tid < 144) {
            cpa16(sd + 2048 + (tid - 128) * 16, Vb + (size_t)bt * VD + (tid - 128) * 4);
        } else if (tid == 144) {
            cpa4(sd + 2304, d_EG + bt * NH + h);
        } else if (tid == 145) {
            cpa4(sd + 2308, d_Beta + bt * NH + h);
        }
    };

#pragma unroll
    for (int p = 0; p < 3; p++) { issue(p, p); CP_COMMIT(); }

    for (int t = 0; t < T_; t++) {
        CP_WAIT2();
        __syncthreads();
        if (t + 3 < T_) issue((t + 3) & 3, t + 3);
        CP_COMMIT();

        const float* sl = ring[t & 3];
        float kf[16], qf[16];
#pragma unroll
        for (int j = 0; j < 4; j++) {
            float4 a = *(const float4*)(sl + rg * 16 + j * 4);
            kf[4 * j] = a.x; kf[4 * j + 1] = a.y; kf[4 * j + 2] = a.z; kf[4 * j + 3] = a.w;
            float4 qd = *(const float4*)(sl + 256 + rg * 16 + j * 4);
            qf[4 * j] = qd.x; qf[4 * j + 1] = qd.y; qf[4 * j + 2] = qd.z; qf[4 * j + 3] = qd.w;
        }
        float4 vv = *(const float4*)(sl + 512 + warp * 8 + cg * 4);
        const float eg = sl[576];
        const float bet = sl[577];

        ull p1a[4] = {0ull, 0ull, 0ull, 0ull};
        ull p1b[4] = {0ull, 0ull, 0ull, 0ull};
#pragma unroll
        for (int j = 0; j < 4; j++)
#pragma unroll
            for (int i = 0; i < 4; i++) {
                const int r = j * 4 + i;
                ull k2 = pack2(kf[r], kf[r]);
                p1a[i] = fma2(k2, S[r][0], p1a[i]);
                p1b[i] = fma2(k2, S[r][1], p1b[i]);
            }
        ull kv2a = add2(add2(p1a[0], p1a[1]), add2(p1a[2], p1a[3]));
        ull kv2b = add2(add2(p1b[0], p1b[1]), add2(p1b[2], p1b[3]));
#pragma unroll
        for (int mask = 2; mask <= 16; mask <<= 1) {
            kv2a = add2(kv2a, __shfl_xor_sync(0xffffffffu, kv2a, mask));
            kv2b = add2(kv2b, __shfl_xor_sync(0xffffffffu, kv2b, mask));
        }
        float kv0, kv1, kv2f, kv3;
        unpack2(kv2a, kv0, kv1);
        unpack2(kv2b, kv2f, kv3);

        ull u2a = pack2((vv.x - eg * kv0) * bet, (vv.y - eg * kv1) * bet);
        ull u2b = pack2((vv.z - eg * kv2f) * bet, (vv.w - eg * kv3) * bet);
        const ull eg2 = pack2(eg, eg);

        ull oa[4] = {0ull, 0ull, 0ull, 0ull};
        ull ob[4] = {0ull, 0ull, 0ull, 0ull};
#pragma unroll
        for (int j = 0; j < 4; j++)
#pragma unroll
            for (int i = 0; i < 4; i++) {
                const int r = j * 4 + i;
                ull k2 = pack2(kf[r], kf[r]);
                ull q2 = pack2(qf[r], qf[r]);
                S[r][0] = fma2(eg2, S[r][0], mul2(k2, u2a));
                oa[i] = fma2(q2, S[r][0], oa[i]);
                S[r][1] = fma2(eg2, S[r][1], mul2(k2, u2b));
                ob[i] = fma2(q2, S[r][1], ob[i]);
            }
        ull o2a = add2(add2(oa[0], oa[1]), add2(oa[2], oa[3]));
        ull o2b = add2(add2(ob[0], ob[1]), add2(ob[2], ob[3]));
#pragma unroll
        for (int mask = 2; mask <= 16; mask <<= 1) {
            o2a = add2(o2a, __shfl_xor_sync(0xffffffffu, o2a, mask));
            o2b = add2(o2b, __shfl_xor_sync(0xffffffffu, o2b, mask));
        }
        if (rg == 0) {
            float4 o4;
            unpack2(o2a, o4.x, o4.y);
            unpack2(o2b, o4.z, o4.w);
            *(float4*)(Ob + (size_t)(bt0 + t) * VD) = o4;
        }
    }
}

// ---------------- gated RMSNorm + operand split (bf16 hi + fp8 h/l) ----------------
__global__ __launch_bounds__(256) void normgate_kernel(const float* __restrict__ w) {
    const int bt = blockIdx.x;
    const int h = blockIdx.y;
    const int tid = threadIdx.x;
    const size_t obase = (size_t)bt * VD + h * DV;
    const size_t gbase = (size_t)bt * PST + GOFF + h * DV;
    float o0 = d_O[obase + tid];
    float o1 = d_O[obase + tid + 256];
    float ss = o0 * o0 + o1 * o1;
    __shared__ float red[8];
#pragma unroll
    for (int m = 16; m > 0; m >>= 1) ss += __shfl_xor_sync(0xffffffffu, ss, m);
    if ((tid & 31) == 0) red[tid >> 5] = ss;
    __syncthreads();
    float tot = 0.0f;
#pragma unroll
    for (int i = 0; i < 8; i++) tot += red[i];
    float rms = rsqrtf(tot * (1.0f / (float)DV) + 1e-5f);
    float g0 = d_P[gbase + tid];
    float g1 = d_P[gbase + tid + 256];
    float r0 = o0 * rms * w[tid]       * g0 * sigm(g0);
    float r1 = o1 * rms * w[tid + 256] * g1 * sigm(g1);
    uint32_t hp = pkbf(r0, r1);
    float h0 = __uint_as_float(hp << 16);
    float h1 = __uint_as_float(hp & 0xffff0000u);
    d_Gh[obase + tid]       = __ushort_as_bfloat16((unsigned short)(hp & 0xffff));
    d_Gh[obase + tid + 256] = __ushort_as_bfloat16((unsigned short)(hp >> 16));
    d_G8h[obase + tid]       = f2e4(r0);
    d_G8h[obase + tid + 256] = f2e4(r1);
    d_G8l[obase + tid]       = f2e4((r0 - h0) * 512.0f);
    d_G8l[obase + tid + 256] = f2e4((r1 - h1) * 512.0f);
}

// ---------------- streams/events ----------------
struct GdnStreams {
    cudaStream_t s1, s2;
    cudaEvent_t evRoot, evW1, evW2, evWo, evGB, evP, evK, evV;
    GdnStreams() {
        cudaStreamCreateWithFlags(&s1, cudaStreamNonBlocking);
        cudaStreamCreateWithFlags(&s2, cudaStreamNonBlocking);
        cudaEventCreateWithFlags(&evRoot, cudaEventDisableTiming);
        cudaEventCreateWithFlags(&evW1, cudaEventDisableTiming);
        cudaEventCreateWithFlags(&evW2, cudaEventDisableTiming);
        cudaEventCreateWithFlags(&evWo, cudaEventDisableTiming);
        cudaEventCreateWithFlags(&evGB, cudaEventDisableTiming);
        cudaEventCreateWithFlags(&evP, cudaEventDisableTiming);
        cudaEventCreateWithFlags(&evK, cudaEventDisableTiming);
        cudaEventCreateWithFlags(&evV, cudaEventDisableTiming);
    }
};
static GdnStreams g_s;

// ---------------- host launcher ----------------
extern "C" void kernel_launch(void* const* d_in, const int* in_sizes, int n_in,
                              void* d_out, int out_size) {
    const float* H       = (const float*)d_in[0];
    const float* Wq      = (const float*)d_in[1];
    const float* Wk      = (const float*)d_in[2];
    const float* Wv      = (const float*)d_in[3];
    const float* Wa      = (const float*)d_in[4];
    const float* Wb      = (const float*)d_in[5];
    const float* Wg      = (const float*)d_in[6];
    const float* Wo      = (const float*)d_in[7];
    const float* conv_q  = (const float*)d_in[8];
    const float* conv_k  = (const float*)d_in[9];
    const float* conv_v  = (const float*)d_in[10];
    const float* A_log   = (const float*)d_in[11];
    const float* dt_bias = (const float*)d_in[12];
    const float* onw     = (const float*)d_in[13];

    float *pp, *qc, *kc;
    cudaGetSymbolAddress((void**)&pp, d_P);
    cudaGetSymbolAddress((void**)&qc, d_Qc);
    cudaGetSymbolAddress((void**)&kc, d_Kc);

    __nv_bfloat16 *hh, *wbh, *woh, *gh;
    uint8_t *h8h, *h8l, *w8h, *w8l, *wo8h, *wo8l, *g8h, *g8l;
    cudaGetSymbolAddress((void**)&hh, d_Hh);
    cudaGetSymbolAddress((void**)&h8h, d_H8h);   cudaGetSymbolAddress((void**)&h8l, d_H8l);
    cudaGetSymbolAddress((void**)&wbh, d_Wbh);
    cudaGetSymbolAddress((void**)&w8h, d_W8h);   cudaGetSymbolAddress((void**)&w8l, d_W8l);
    cudaGetSymbolAddress((void**)&woh, d_Woh);
    cudaGetSymbolAddress((void**)&wo8h, d_Wo8h); cudaGetSymbolAddress((void**)&wo8l, d_Wo8l);
    cudaGetSymbolAddress((void**)&gh, d_Gh);
    cudaGetSymbolAddress((void**)&g8h, d_G8h);   cudaGetSymbolAddress((void**)&g8l, d_G8l);

    cudaFuncSetAttribute(gemm_bf8, cudaFuncAttributeMaxDynamicSharedMemorySize, SMEM_GB);

    cudaStream_t s0 = 0;
    cudaStream_t s1 = g_s.s1, s2 = g_s.s2;

    // ---- fork ----
    cudaEventRecord(g_s.evRoot, s0);
    cudaStreamWaitEvent(s1, g_s.evRoot, 0);
    cudaStreamWaitEvent(s2, g_s.evRoot, 0);

    // s0: split H (bf16 hi + fp8 h/l)
    {
        int n4 = (BT * HID) / 4;
        splitA_kernel<<<(n4 + 255) / 256, 256, 0, s0>>>((const float4*)H, (uint2*)hh,
                                                        (uint32_t*)h8h, (uint32_t*)h8l, n4);
    }
    // s1: bf16-hi weight splits (concat) + fp8 transposes for Wq,Wk
    {
        int n4q = (HID * KD) / 4;
        splitWh_s<<<(n4q + 255) / 256, 256, 0, s1>>>((const float4*)Wq, wbh, n4q, KD / 4, QOFF);
        splitWh_s<<<(n4q + 255) / 256, 256, 0, s1>>>((const float4*)Wk, wbh, n4q, KD / 4, KOFF);
        int n4v = (HID * VD) / 4;
        splitWh_s<<<(n4v + 255) / 256, 256, 0, s1>>>((const float4*)Wv, wbh, n4v, VD / 4, VOFF);
        splitWh_s<<<(n4v + 255) / 256, 256, 0, s1>>>((const float4*)Wg, wbh, n4v, VD / 4, GOFF);
        transW8_kernel<<<dim3(KD / 32, HID / 32), 256, 0, s1>>>(Wq, (uint32_t*)w8h, (uint32_t*)w8l, HID, KD, QOFF);
        transW8_kernel<<<dim3(KD / 32, HID / 32), 256, 0, s1>>>(Wk, (uint32_t*)w8h, (uint32_t*)w8l, HID, KD, KOFF);
        cudaEventRecord(g_s.evW1, s1);
    }
    // s2: fp8 transposes for Wv,Wg + Wo splits + gate
    {
        transW8_kernel<<<dim3(VD / 32, HID / 32), 256, 0, s2>>>(Wv, (uint32_t*)w8h, (uint32_t*)w8l, HID, VD, VOFF);
        transW8_kernel<<<dim3(VD / 32, HID / 32), 256, 0, s2>>>(Wg, (uint32_t*)w8h, (uint32_t*)w8l, HID, VD, GOFF);
        cudaEventRecord(g_s.evW2, s2);
        int n4o = (VD * HID) / 4;
        splitWh_c<<<(n4o + 255) / 256, 256, 0, s2>>>((const float4*)Wo, (uint2*)woh, n4o);
        transW8_kernel<<<dim3(HID / 32, VD / 32), 256, 0, s2>>>(Wo, (uint32_t*)wo8h, (uint32_t*)wo8l, VD, HID, 0);
        cudaEventRecord(g_s.evWo, s2);
        gate_kernel<<<BT, 256, 0, s2>>>(H, Wa, Wb, A_log, dt_bias);
        cudaEventRecord(g_s.evGB, s2);
    }

    // ---- ONE fused QKVG projection GEMM: [4096 x 9216] ----
    cudaStreamWaitEvent(s0, g_s.evW1, 0);
    cudaStreamWaitEvent(s0, g_s.evW2, 0);
    gemm_bf8<<<dim3(PST / BN, BT / BM), 256, SMEM_GB, s0>>>(hh, h8h, h8l, wbh, w8h, w8l,
                                                            pp, BT, HID, PST, PST);
    cudaEventRecord(g_s.evP, s0);

    // ---- convs (3-way concurrent) ----
    convqk_kernel<<<dim3(BT, NH), 256, 0, s0>>>(pp, conv_q, qc, 0.0625f, QOFF);
    cudaStreamWaitEvent(s1, g_s.evP, 0);
    convqk_kernel<<<dim3(BT, NH), 256, 0, s1>>>(pp, conv_k, kc, 1.0f, KOFF);
    cudaEventRecord(g_s.evK, s1);
    cudaStreamWaitEvent(s2, g_s.evP, 0);
    convv_kernel<<<dim3(BT, VD / 256), 256, 0, s2>>>(pp, conv_v);
    cudaEventRecord(g_s.evV, s2);

    // ---- recurrence ----
    cudaStreamWaitEvent(s0, g_s.evK, 0);
    cudaStreamWaitEvent(s0, g_s.evV, 0);
    cudaStreamWaitEvent(s0, g_s.evGB, 0);
    recur_kernel<<<96, 256, 0, s0>>>();

    // ---- epilogue: fused normgate+split, then Wo GEMM ----
    normgate_kernel<<<dim3(BT, NH), 256, 0, s0>>>(onw);
    cudaStreamWaitEvent(s0, g_s.evWo, 0);
    gemm_bf8<<<dim3(HID / BN, BT / BM), 256, SMEM_GB, s0>>>(gh, g8h, g8l, woh, wo8h, wo8l,
                                                            (float*)d_out, BT, VD, HID, HID);
}

// round 13
// speedup vs baseline: 1.1976x; 1.1976x over previous
#include <cuda_runtime.h>
#include <cuda_bf16.h>
#include <cstdint>

// ---------------- problem dims ----------------
#define B_   2
#define T_   2048
#define HID  2048
#define NH   6
#define DK   256
#define DV   512
#define KD   1536      // NH*DK
#define VD   3072      // NH*DV
#define BT   4096      // B_*T_
#define CK   4

// fused projection layout: [q(1536) | k(1536) | v(3072) | g(3072)]
#define PST  9216
#define QOFF 0
#define KOFF 1536
#define VOFF 3072
#define GOFF 6144

typedef unsigned long long ull;

// ---------------- scratch (device globals; no allocs allowed) ----------------
__device__ float d_P[(size_t)BT * PST];       // fused projection output (fp32)
__device__ float d_Qc[BT * KD];
__device__ float d_Kc[BT * KD];
__device__ float d_Vc[(size_t)BT * VD];
__device__ float d_EG[BT * NH];
__device__ float d_Beta[BT * NH];
__device__ float d_O[(size_t)BT * VD];

// bf16 split operand buffers
__device__ __nv_bfloat16 d_Hh[(size_t)BT * HID];
__device__ __nv_bfloat16 d_Hl[(size_t)BT * HID];
__device__ __nv_bfloat16 d_Wbh[(size_t)HID * PST];   // [Wq|Wk|Wv|Wg] hi
__device__ __nv_bfloat16 d_Wbl[(size_t)HID * PST];   // lo
__device__ __nv_bfloat16 d_Woh[(size_t)VD * HID];
__device__ __nv_bfloat16 d_Wol[(size_t)VD * HID];
__device__ __nv_bfloat16 d_Gh[(size_t)BT * VD];
__device__ __nv_bfloat16 d_Gl[(size_t)BT * VD];

// ---------------- packed f32x2 helpers (recurrence) ----------------
__device__ __forceinline__ ull fma2(ull a, ull b, ull c) {
    ull d;
    asm("fma.rn.f32x2 %0, %1, %2, %3;" : "=l"(d) : "l"(a), "l"(b), "l"(c));
    return d;
}
__device__ __forceinline__ ull mul2(ull a, ull b) {
    ull d;
    asm("mul.rn.f32x2 %0, %1, %2;" : "=l"(d) : "l"(a), "l"(b));
    return d;
}
__device__ __forceinline__ ull add2(ull a, ull b) {
    ull d;
    asm("add.rn.f32x2 %0, %1, %2;" : "=l"(d) : "l"(a), "l"(b));
    return d;
}
__device__ __forceinline__ ull pack2(float lo, float hi) {
    ull d;
    asm("mov.b64 %0, {%1, %2};" : "=l"(d) : "f"(lo), "f"(hi));
    return d;
}
__device__ __forceinline__ void unpack2(ull v, float& lo, float& hi) {
    asm("mov.b64 {%0, %1}, %2;" : "=f"(lo), "=f"(hi) : "l"(v));
}
__device__ __forceinline__ float sigm(float x) { return 1.0f / (1.0f + __expf(-x)); }

// ---------------- mma.sync bf16 GEMM machinery ----------------
__device__ __forceinline__ uint32_t smem_u32(const void* p) {
    uint32_t a;
    asm("{ .reg .u64 t; cvta.to.shared.u64 t, %1; cvt.u32.u64 %0, t; }" : "=r"(a) : "l"(p));
    return a;
}
__device__ __forceinline__ uint32_t pkbf(float x, float y) {
    uint32_t r;
    asm("cvt.rn.bf16x2.f32 %0, %1, %2;" : "=r"(r) : "f"(y), "f"(x));
    return r;
}
__device__ __forceinline__ void ldsm_x4(uint32_t* r, uint32_t a) {
    asm volatile("ldmatrix.sync.aligned.m8n8.x4.shared.b16 {%0,%1,%2,%3}, [%4];"
                 : "=r"(r[0]), "=r"(r[1]), "=r"(r[2]), "=r"(r[3]) : "r"(a));
}
__device__ __forceinline__ void ldsm_x4_t(uint32_t* r, uint32_t a) {
    asm volatile("ldmatrix.sync.aligned.m8n8.x4.trans.shared.b16 {%0,%1,%2,%3}, [%4];"
                 : "=r"(r[0]), "=r"(r[1]), "=r"(r[2]), "=r"(r[3]) : "r"(a));
}
__device__ __forceinline__ void mma_bf16(float* d, const uint32_t* a, const uint32_t* b) {
    asm volatile(
        "mma.sync.aligned.m16n8k16.row.col.f32.bf16.bf16.f32 "
        "{%0,%1,%2,%3}, {%4,%5,%6,%7}, {%8,%9}, {%0,%1,%2,%3};"
        : "+f"(d[0]), "+f"(d[1]), "+f"(d[2]), "+f"(d[3])
        : "r"(a[0]), "r"(a[1]), "r"(a[2]), "r"(a[3]), "r"(b[0]), "r"(b[1]));
}
__device__ __forceinline__ void cpa16(uint32_t dst, const void* src) {
    asm volatile("cp.async.cg.shared.global [%0], [%1], 16;" :: "r"(dst), "l"(src));
}
__device__ __forceinline__ void cpa4(uint32_t dst, const void* src) {
    asm volatile("cp.async.ca.shared.global [%0], [%1], 4;" :: "r"(dst), "l"(src));
}
#define CP_COMMIT() asm volatile("cp.async.commit_group;" ::: "memory")
#define CP_WAIT1()  asm volatile("cp.async.wait_group 1;" ::: "memory")
#define CP_WAIT2()  asm volatile("cp.async.wait_group 2;" ::: "memory")

// tiles: 128(M) x 64(N), BK=32, 3 stages, 2 CTAs/SM
#define BM 128
#define BN 64
#define BKf 32
#define STAGES 3
#define A_STR 80
#define B_STR 144
#define AT_BYTES (128 * A_STR)
#define BTI_BYTES (32 * B_STR)
#define OFF_AH 0
#define OFF_AL AT_BYTES
#define OFF_BH (2 * AT_BYTES)
#define OFF_BL (2 * AT_BYTES + BTI_BYTES)
#define STAGE_BYTES (2 * AT_BYTES + 2 * BTI_BYTES)
#define SMEM_GB (STAGES * STAGE_BYTES)

__device__ __forceinline__ void g_issue(uint32_t st,
                                        const __nv_bfloat16* __restrict__ Ah,
                                        const __nv_bfloat16* __restrict__ Al,
                                        const __nv_bfloat16* __restrict__ Bh,
                                        const __nv_bfloat16* __restrict__ Bl,
                                        int m0, int n0, int kt, int K, int N, int tid) {
#pragma unroll
    for (int half = 0; half < 2; half++) {
        int r = (tid >> 2) + half * 64;
        int ke = (tid & 3) * 8;
        const size_t ga = (size_t)(m0 + r) * K + kt * BKf + ke;
        uint32_t so = st + r * A_STR + ke * 2;
        cpa16(so + OFF_AH, Ah + ga);
        cpa16(so + OFF_AL, Al + ga);
    }
    {
        int r = tid >> 3;
        int ke = (tid & 7) * 8;
        const size_t gb = (size_t)(kt * BKf + r) * N + n0 + ke;
        uint32_t so = st + r * B_STR + ke * 2;
        cpa16(so + OFF_BH, Bh + gb);
        cpa16(so + OFF_BL, Bl + gb);
    }
}

__device__ __forceinline__ void g_compute(uint32_t st, int wid, int lane, float (*acc)[4][4]) {
    const int wm = (wid & 3) * 32, wn = (wid >> 2) * 32;
    const int arow = lane & 15;
    const int acg = (lane >> 4) * 8;
    const int brow = (lane & 7) + ((lane >> 3) & 1) * 8;
    const int bcg = (lane >> 4) * 8;
#pragma unroll
    for (int ks = 0; ks < BKf; ks += 16) {
        uint32_t ah[2][4], al[2][4], bh[2][4], bl[2][4];
#pragma unroll
        for (int mt = 0; mt < 2; mt++) {
            uint32_t ad = st + OFF_AH + (wm + mt * 16 + arow) * A_STR + (ks + acg) * 2;
            ldsm_x4(ah[mt], ad);
            ldsm_x4(al[mt], ad + (OFF_AL - OFF_AH));
        }
#pragma unroll
        for (int nt = 0; nt < 2; nt++) {
            uint32_t bd = st + OFF_BH + (ks + brow) * B_STR + (wn + nt * 16 + bcg) * 2;
            ldsm_x4_t(bh[nt], bd);
            ldsm_x4_t(bl[nt], bd + (OFF_BL - OFF_BH));
        }
#pragma unroll
        for (int mt = 0; mt < 2; mt++)
#pragma unroll
            for (int j = 0; j < 4; j++)
                mma_bf16(acc[mt][j], ah[mt], &bh[j >> 1][(j & 1) * 2]);
#pragma unroll
        for (int mt = 0; mt < 2; mt++)
#pragma unroll
            for (int j = 0; j < 4; j++)
                mma_bf16(acc[mt][j], ah[mt], &bl[j >> 1][(j & 1) * 2]);
#pragma unroll
        for (int mt = 0; mt < 2; mt++)
#pragma unroll
            for (int j = 0; j < 4; j++)
                mma_bf16(acc[mt][j], al[mt], &bh[j >> 1][(j & 1) * 2]);
    }
}

// C[M,N] = A[M,K] @ B[K,N]; operands pre-split hi/lo bf16, fp32 out
__global__ __launch_bounds__(256, 2) void gemm_bf(const __nv_bfloat16* __restrict__ Ah,
                                                  const __nv_bfloat16* __restrict__ Al,
                                                  const __nv_bfloat16* __restrict__ Bh,
                                                  const __nv_bfloat16* __restrict__ Bl,
                                                  float* __restrict__ C,
                                                  int M, int N, int K) {
    extern __shared__ char smem[];
    const uint32_t sb = smem_u32(smem);
    const int tid = threadIdx.x, lane = tid & 31, wid = tid >> 5;
    const int m0 = blockIdx.y * BM, n0 = blockIdx.x * BN;
    const int NT = K / BKf;

    float acc[2][4][4];
#pragma unroll
    for (int mt = 0; mt < 2; mt++)
#pragma unroll
        for (int j = 0; j < 4; j++)
#pragma unroll
            for (int p = 0; p < 4; p++) acc[mt][j][p] = 0.0f;

    g_issue(sb, Ah, Al, Bh, Bl, m0, n0, 0, K, N, tid);
    CP_COMMIT();
    g_issue(sb + STAGE_BYTES, Ah, Al, Bh, Bl, m0, n0, 1, K, N, tid);
    CP_COMMIT();

    for (int kt = 0; kt < NT; kt++) {
        CP_WAIT1();
        __syncthreads();
        const int pf = kt + 2;
        if (pf < NT)
            g_issue(sb + (pf % STAGES) * STAGE_BYTES, Ah, Al, Bh, Bl, m0, n0, pf, K, N, tid);
        CP_COMMIT();
        g_compute(sb + (kt % STAGES) * STAGE_BYTES, wid, lane, acc);
    }

    const int wm = (wid & 3) * 32, wn = (wid >> 2) * 32;
    const int g = lane >> 2, t = lane & 3;
#pragma unroll
    for (int mt = 0; mt < 2; mt++)
#pragma unroll
        for (int j = 0; j < 4; j++) {
            float* p = C + (size_t)(m0 + wm + mt * 16 + g) * N + n0 + wn + j * 8 + t * 2;
            float2 c0 = make_float2(acc[mt][j][0], acc[mt][j][1]);
            float2 c1 = make_float2(acc[mt][j][2], acc[mt][j][3]);
            *(float2*)p = c0;
            *(float2*)(p + (size_t)8 * N) = c1;
        }
}

// ---------------- hi/lo bf16 split (contiguous) ----------------
__global__ __launch_bounds__(256) void split_kernel(const float4* __restrict__ src,
                                                    uint2* __restrict__ h,
                                                    uint2* __restrict__ l, int n4) {
    int i = blockIdx.x * 256 + threadIdx.x;
    if (i >= n4) return;
    float4 v = src[i];
    uint32_t h01 = pkbf(v.x, v.y), h23 = pkbf(v.z, v.w);
    float hx = __uint_as_float(h01 << 16);
    float hy = __uint_as_float(h01 & 0xffff0000u);
    float hz = __uint_as_float(h23 << 16);
    float hw = __uint_as_float(h23 & 0xffff0000u);
    h[i] = make_uint2(h01, h23);
    l[i] = make_uint2(pkbf(v.x - hx, v.y - hy), pkbf(v.z - hz, v.w - hw));
}

// ---------------- hi/lo bf16 split into strided (concatenated) dest ----------------
__global__ __launch_bounds__(256) void splitWs_kernel(const float4* __restrict__ src,
                                                      __nv_bfloat16* __restrict__ dh,
                                                      __nv_bfloat16* __restrict__ dl,
                                                      int n4, int ncols4, int colOff) {
    int i = blockIdx.x * 256 + threadIdx.x;
    if (i >= n4) return;
    int row = i / ncols4;
    int c4 = i - row * ncols4;
    float4 v = src[i];
    uint32_t h01 = pkbf(v.x, v.y), h23 = pkbf(v.z, v.w);
    float hx = __uint_as_float(h01 << 16);
    float hy = __uint_as_float(h01 & 0xffff0000u);
    float hz = __uint_as_float(h23 << 16);
    float hw = __uint_as_float(h23 & 0xffff0000u);
    size_t o = (size_t)row * PST + colOff + c4 * 4;
    *(uint2*)(dh + o) = make_uint2(h01, h23);
    *(uint2*)(dl + o) = make_uint2(pkbf(v.x - hx, v.y - hy), pkbf(v.z - hz, v.w - hw));
}

// ---------------- gate projections: g -> exp(g), beta ----------------
__global__ __launch_bounds__(256) void gate_kernel(const float* __restrict__ H,
                                                   const float* __restrict__ Wa,
                                                   const float* __restrict__ Wb,
                                                   const float* __restrict__ A_log,
                                                   const float* __restrict__ dt_bias) {
    __shared__ float hrow[HID];
    const int bt = blockIdx.x;
    const int tid = threadIdx.x;
    for (int i = tid; i < HID; i += 256) hrow[i] = H[(size_t)bt * HID + i];
    __syncthreads();
    const int w = tid >> 5, lane = tid & 31;
    for (int d = w; d < 12; d += 8) {
        const int head = d % 6;
        const float* Wc = (d < 6) ? Wa : Wb;
        float s = 0.0f;
        for (int i = lane; i < HID; i += 32) s += hrow[i] * Wc[i * NH + head];
#pragma unroll
        for (int m = 16; m > 0; m >>= 1) s += __shfl_xor_sync(0xffffffffu, s, m);
        if (lane == 0) {
            if (d < 6) {
                float x = s + dt_bias[head];
                float sp = (x > 20.0f) ? x : log1pf(expf(x));
                float g = -expf(A_log[head]) * sp;
                d_EG[bt * NH + head] = expf(g);
            } else {
                d_Beta[bt * NH + head] = sigm(s);
            }
        }
    }
}

// ---------------- causal depthwise conv + silu + per-head l2norm (q/k) ----------------
__global__ __launch_bounds__(256) void convqk_kernel(const float* __restrict__ P,
                                                     const float* __restrict__ W,
                                                     float* __restrict__ out,
                                                     float scale, int colOff) {
    const int bt = blockIdx.x;
    const int h = blockIdx.y;
    const int c = threadIdx.x;
    const int ch = h * DK + c;
    const int t = bt & (T_ - 1);
    float acc = 0.0f;
#pragma unroll
    for (int j = 0; j < CK; j++) {
        int tt = t - (CK - 1) + j;
        if (tt >= 0) acc += P[(size_t)(bt - (CK - 1) + j) * PST + colOff + ch] * W[ch * CK + j];
    }
    float y = acc * sigm(acc);  // silu

    __shared__ float red[8];
    float ss = y * y;
#pragma unroll
    for (int m = 16; m > 0; m >>= 1) ss += __shfl_xor_sync(0xffffffffu, ss, m);
    if ((c & 31) == 0) red[c >> 5] = ss;
    __syncthreads();
    float tot = 0.0f;
#pragma unroll
    for (int i = 0; i < 8; i++) tot += red[i];
    float r = rsqrtf(tot + 1e-6f);
    out[(size_t)bt * KD + ch] = y * r * scale;
}

// ---------------- causal depthwise conv + silu (v) ----------------
__global__ __launch_bounds__(256) void convv_kernel(const float* __restrict__ P,
                                                    const float* __restrict__ W) {
    const int bt = blockIdx.x;
    const int ch = blockIdx.y * 256 + threadIdx.x;
    const int t = bt & (T_ - 1);
    float acc = 0.0f;
#pragma unroll
    for (int j = 0; j < CK; j++) {
        int tt = t - (CK - 1) + j;
        if (tt >= 0) acc += P[(size_t)(bt - (CK - 1) + j) * PST + VOFF + ch] * W[ch * CK + j];
    }
    d_Vc[(size_t)bt * VD + ch] = acc * sigm(acc);
}

// ---------------- gated delta-rule recurrence (cp.async smem ring, 4-way ILP) ----------------
// 96 CTAs: (b,h) x 8 chunks of 64 cols. warp owns 8 cols; lane=(rg,cg):
// rg 0..15 -> 16 rows; cg 0..1 -> 4 cols. Ring: 4 slots of {k256,q256,v64,eg,beta}.
#define RSLOT 640   // floats per slot (2560B)
__global__ __launch_bounds__(256, 1) void recur_kernel() {
    __shared__ __align__(16) float ring[4][RSLOT];
    const int bid = blockIdx.x;
    const int chunk = bid & 7;
    const int bh = bid >> 3;
    const int b = bh / NH, h = bh % NH;
    const int tid = threadIdx.x;
    const int warp = tid >> 5, lane = tid & 31;
    const int rg = lane >> 1, cg = lane & 1;
    const int bt0 = b * T_;

    const float* Kb = d_Kc + h * DK;
    const float* Qb = d_Qc + h * DK;
    const float* Vb = d_Vc + h * DV + chunk * 64;
    float* Ob = d_O + h * DV + chunk * 64 + warp * 8 + cg * 4;

    ull S[16][2];
#pragma unroll
    for (int r = 0; r < 16; r++) { S[r][0] = 0ull; S[r][1] = 0ull; }

    // producer: each thread issues <=1 cp.async per timestep
    auto issue = [&](int slot, int t) {
        const int bt = bt0 + t;
        uint32_t sd = smem_u32(&ring[slot][0]);
        if (tid < 64) {
            cpa16(sd + tid * 16, Kb + (size_t)bt * KD + tid * 4);
        } else if (tid < 128) {
            cpa16(sd + 1024 + (tid - 64) * 16, Qb + (size_t)bt * KD + (tid - 64) * 4);
        } else if (tid < 144) {
            cpa16(sd + 2048 + (tid - 128) * 16, Vb + (size_t)bt * VD + (tid - 128) * 4);
        } else if (tid == 144) {
            cpa4(sd + 2304, d_EG + bt * NH + h);
        } else if (tid == 145) {
            cpa4(sd + 2308, d_Beta + bt * NH + h);
        }
    };

    // prime slots 0..2
#pragma unroll
    for (int p = 0; p < 3; p++) { issue(p, p); CP_COMMIT(); }

    for (int t = 0; t < T_; t++) {
        CP_WAIT2();
        __syncthreads();
        if (t + 3 < T_) issue((t + 3) & 3, t + 3);
        CP_COMMIT();

        const float* sl = ring[t & 3];
        // load k and pre-pack into f32x2 broadcast form (used in BOTH phases)
        ull k2[16];
        float qf[16];
#pragma unroll
        for (int j = 0; j < 4; j++) {
            float4 a = *(const float4*)(sl + rg * 16 + j * 4);
            k2[4 * j]     = pack2(a.x, a.x);
            k2[4 * j + 1] = pack2(a.y, a.y);
            k2[4 * j + 2] = pack2(a.z, a.z);
            k2[4 * j + 3] = pack2(a.w, a.w);
            float4 qd = *(const float4*)(sl + 256 + rg * 16 + j * 4);
            qf[4 * j] = qd.x; qf[4 * j + 1] = qd.y; qf[4 * j + 2] = qd.z; qf[4 * j + 3] = qd.w;
        }
        float4 vv = *(const float4*)(sl + 512 + warp * 8 + cg * 4);
        const float eg = sl[576];
        const float bet = sl[577];

        // phase 1: kv = k . S (pre-decay), 4 parallel accumulators
        ull p1a[4] = {0ull, 0ull, 0ull, 0ull};
        ull p1b[4] = {0ull, 0ull, 0ull, 0ull};
#pragma unroll
        for (int j = 0; j < 4; j++)
#pragma unroll
            for (int i = 0; i < 4; i++) {
                const int r = j * 4 + i;
                p1a[i] = fma2(k2[r], S[r][0], p1a[i]);
                p1b[i] = fma2(k2[r], S[r][1], p1b[i]);
            }
        ull kv2a = add2(add2(p1a[0], p1a[1]), add2(p1a[2], p1a[3]));
        ull kv2b = add2(add2(p1b[0], p1b[1]), add2(p1b[2], p1b[3]));
#pragma unroll
        for (int mask = 2; mask <= 16; mask <<= 1) {
            kv2a = add2(kv2a, __shfl_xor_sync(0xffffffffu, kv2a, mask));
            kv2b = add2(kv2b, __shfl_xor_sync(0xffffffffu, kv2b, mask));
        }
        float kv0, kv1, kv2f, kv3;
        unpack2(kv2a, kv0, kv1);
        unpack2(kv2b, kv2f, kv3);

        ull u2a = pack2((vv.x - eg * kv0) * bet, (vv.y - eg * kv1) * bet);
        ull u2b = pack2((vv.z - eg * kv2f) * bet, (vv.w - eg * kv3) * bet);
        const ull eg2 = pack2(eg, eg);

        // phase 2: S = eg*S + k (x) u ; o = q . S, 4 parallel accumulators
        ull oa[4] = {0ull, 0ull, 0ull, 0ull};
        ull ob[4] = {0ull, 0ull, 0ull, 0ull};
#pragma unroll
        for (int j = 0; j < 4; j++)
#pragma unroll
            for (int i = 0; i < 4; i++) {
                const int r = j * 4 + i;
                ull q2 = pack2(qf[r], qf[r]);
                S[r][0] = fma2(eg2, S[r][0], mul2(k2[r], u2a));
                oa[i] = fma2(q2, S[r][0], oa[i]);
                S[r][1] = fma2(eg2, S[r][1], mul2(k2[r], u2b));
                ob[i] = fma2(q2, S[r][1], ob[i]);
            }
        ull o2a = add2(add2(oa[0], oa[1]), add2(oa[2], oa[3]));
        ull o2b = add2(add2(ob[0], ob[1]), add2(ob[2], ob[3]));
#pragma unroll
        for (int mask = 2; mask <= 16; mask <<= 1) {
            o2a = add2(o2a, __shfl_xor_sync(0xffffffffu, o2a, mask));
            o2b = add2(o2b, __shfl_xor_sync(0xffffffffu, o2b, mask));
        }
        if (rg == 0) {
            float4 o4;
            unpack2(o2a, o4.x, o4.y);
            unpack2(o2b, o4.z, o4.w);
            *(float4*)(Ob + (size_t)(bt0 + t) * VD) = o4;
        }
    }
}

// ---------------- gated RMSNorm + bf16 hi/lo split (fused) ----------------
__global__ __launch_bounds__(256) void normgate_kernel(const float* __restrict__ w) {
    const int bt = blockIdx.x;
    const int h = blockIdx.y;
    const int tid = threadIdx.x;
    const size_t obase = (size_t)bt * VD + h * DV;
    const size_t gbase = (size_t)bt * PST + GOFF + h * DV;
    float o0 = d_O[obase + tid];
    float o1 = d_O[obase + tid + 256];
    float ss = o0 * o0 + o1 * o1;
    __shared__ float red[8];
#pragma unroll
    for (int m = 16; m > 0; m >>= 1) ss += __shfl_xor_sync(0xffffffffu, ss, m);
    if ((tid & 31) == 0) red[tid >> 5] = ss;
    __syncthreads();
    float tot = 0.0f;
#pragma unroll
    for (int i = 0; i < 8; i++) tot += red[i];
    float rms = rsqrtf(tot * (1.0f / (float)DV) + 1e-5f);
    float g0 = d_P[gbase + tid];
    float g1 = d_P[gbase + tid + 256];
    float r0 = o0 * rms * w[tid]       * g0 * sigm(g0);
    float r1 = o1 * rms * w[tid + 256] * g1 * sigm(g1);
    // fused bf16 hi/lo split
    uint32_t hp = pkbf(r0, r1);
    float h0 = __uint_as_float(hp << 16);
    float h1 = __uint_as_float(hp & 0xffff0000u);
    uint32_t lp = pkbf(r0 - h0, r1 - h1);
    d_Gh[obase + tid]       = __ushort_as_bfloat16((unsigned short)(hp & 0xffff));
    d_Gh[obase + tid + 256] = __ushort_as_bfloat16((unsigned short)(hp >> 16));
    d_Gl[obase + tid]       = __ushort_as_bfloat16((unsigned short)(lp & 0xffff));
    d_Gl[obase + tid + 256] = __ushort_as_bfloat16((unsigned short)(lp >> 16));
}

// ---------------- streams/events (created once at static init) ----------------
struct GdnStreams {
    cudaStream_t s1, s2;
    cudaEvent_t evRoot, evW, evGB, evP, evK, evV;
    GdnStreams() {
        cudaStreamCreateWithFlags(&s1, cudaStreamNonBlocking);
        cudaStreamCreateWithFlags(&s2, cudaStreamNonBlocking);
        cudaEventCreateWithFlags(&evRoot, cudaEventDisableTiming);
        cudaEventCreateWithFlags(&evW, cudaEventDisableTiming);
        cudaEventCreateWithFlags(&evGB, cudaEventDisableTiming);
        cudaEventCreateWithFlags(&evP, cudaEventDisableTiming);
        cudaEventCreateWithFlags(&evK, cudaEventDisableTiming);
        cudaEventCreateWithFlags(&evV, cudaEventDisableTiming);
    }
};
static GdnStreams g_s;

// ---------------- host launcher ----------------
extern "C" void kernel_launch(void* const* d_in, const int* in_sizes, int n_in,
                              void* d_out, int out_size) {
    const float* H       = (const float*)d_in[0];
    const float* Wq      = (const float*)d_in[1];
    const float* Wk      = (const float*)d_in[2];
    const float* Wv      = (const float*)d_in[3];
    const float* Wa      = (const float*)d_in[4];
    const float* Wb      = (const float*)d_in[5];
    const float* Wg      = (const float*)d_in[6];
    const float* Wo      = (const float*)d_in[7];
    const float* conv_q  = (const float*)d_in[8];
    const float* conv_k  = (const float*)d_in[9];
    const float* conv_v  = (const float*)d_in[10];
    const float* A_log   = (const float*)d_in[11];
    const float* dt_bias = (const float*)d_in[12];
    const float* onw     = (const float*)d_in[13];

    float *pp, *qc, *kc;
    cudaGetSymbolAddress((void**)&pp, d_P);
    cudaGetSymbolAddress((void**)&qc, d_Qc);
    cudaGetSymbolAddress((void**)&kc, d_Kc);

    __nv_bfloat16 *hh, *hl, *wbh, *wbl, *woh, *wol, *gh, *gl;
    cudaGetSymbolAddress((void**)&hh, d_Hh);   cudaGetSymbolAddress((void**)&hl, d_Hl);
    cudaGetSymbolAddress((void**)&wbh, d_Wbh); cudaGetSymbolAddress((void**)&wbl, d_Wbl);
    cudaGetSymbolAddress((void**)&woh, d_Woh); cudaGetSymbolAddress((void**)&wol, d_Wol);
    cudaGetSymbolAddress((void**)&gh, d_Gh);   cudaGetSymbolAddress((void**)&gl, d_Gl);

    cudaFuncSetAttribute(gemm_bf, cudaFuncAttributeMaxDynamicSharedMemorySize, SMEM_GB);

    cudaStream_t s0 = 0;
    cudaStream_t s1 = g_s.s1, s2 = g_s.s2;

    // ---- fork: root event on origin stream so side streams join the capture ----
    cudaEventRecord(g_s.evRoot, s0);
    cudaStreamWaitEvent(s1, g_s.evRoot, 0);
    cudaStreamWaitEvent(s2, g_s.evRoot, 0);

    // s0: split H
    {
        int n4 = (BT * HID) / 4;
        split_kernel<<<(n4 + 255) / 256, 256, 0, s0>>>((const float4*)H, (uint2*)hh, (uint2*)hl, n4);
    }
    // s1: weight splits into concatenated buffer + Wo split (independent of H)
    {
        int n4q = (HID * KD) / 4;
        splitWs_kernel<<<(n4q + 255) / 256, 256, 0, s1>>>((const float4*)Wq, wbh, wbl, n4q, KD / 4, QOFF);
        splitWs_kernel<<<(n4q + 255) / 256, 256, 0, s1>>>((const float4*)Wk, wbh, wbl, n4q, KD / 4, KOFF);
        int n4v = (HID * VD) / 4;
        splitWs_kernel<<<(n4v + 255) / 256, 256, 0, s1>>>((const float4*)Wv, wbh, wbl, n4v, VD / 4, VOFF);
        splitWs_kernel<<<(n4v + 255) / 256, 256, 0, s1>>>((const float4*)Wg, wbh, wbl, n4v, VD / 4, GOFF);
        int n4o = (VD * HID) / 4;
        split_kernel<<<(n4o + 255) / 256, 256, 0, s1>>>((const float4*)Wo, (uint2*)woh, (uint2*)wol, n4o);
        cudaEventRecord(g_s.evW, s1);
    }
    // s2: gate projections (reads raw H)
    gate_kernel<<<BT, 256, 0, s2>>>(H, Wa, Wb, A_log, dt_bias);
    cudaEventRecord(g_s.evGB, s2);

    // ---- ONE fused projection GEMM: [4096 x 9216] ----
    cudaStreamWaitEvent(s0, g_s.evW, 0);
    gemm_bf<<<dim3(PST / BN, BT / BM), 256, SMEM_GB, s0>>>(hh, hl, wbh, wbl, pp, BT, PST, HID);
    cudaEventRecord(g_s.evP, s0);

    // ---- convs (3-way concurrent) ----
    convqk_kernel<<<dim3(BT, NH), 256, 0, s0>>>(pp, conv_q, qc, 0.0625f, QOFF);
    cudaStreamWaitEvent(s1, g_s.evP, 0);
    convqk_kernel<<<dim3(BT, NH), 256, 0, s1>>>(pp, conv_k, kc, 1.0f, KOFF);
    cudaEventRecord(g_s.evK, s1);
    cudaStreamWaitEvent(s2, g_s.evP, 0);
    convv_kernel<<<dim3(BT, VD / 256), 256, 0, s2>>>(pp, conv_v);
    cudaEventRecord(g_s.evV, s2);

    // ---- recurrence ----
    cudaStreamWaitEvent(s0, g_s.evK, 0);
    cudaStreamWaitEvent(s0, g_s.evV, 0);
    cudaStreamWaitEvent(s0, g_s.evGB, 0);
    recur_kernel<<<96, 256, 0, s0>>>();

    // ---- epilogue: fused normgate+split, then Wo GEMM ----
    normgate_kernel<<<dim3(BT, NH), 256, 0, s0>>>(onw);
    gemm_bf<<<dim3(HID / BN, BT / BM), 256, SMEM_GB, s0>>>(gh, gl, woh, wol, (float*)d_out, BT, HID, VD);
}

// round 14
// speedup vs baseline: 1.2478x; 1.0419x over previous
#include <cuda_runtime.h>
#include <cuda_bf16.h>
#include <cstdint>

// ---------------- problem dims ----------------
#define B_   2
#define T_   2048
#define HID  2048
#define NH   6
#define DK   256
#define DV   512
#define KD   1536      // NH*DK
#define VD   3072      // NH*DV
#define BT   4096      // B_*T_
#define CK   4

// fused projection layout: [q(1536) | k(1536) | v(3072) | g(3072)]
#define PST  9216
#define QOFF 0
#define KOFF 1536
#define VOFF 3072
#define GOFF 6144

typedef unsigned long long ull;

// ---------------- scratch (device globals; no allocs allowed) ----------------
__device__ float d_P[(size_t)BT * PST];       // fused projection output (fp32)
__device__ float d_Qc[BT * KD];
__device__ float d_Kc[BT * KD];
__device__ float d_Vc[(size_t)BT * VD];
__device__ float d_EG[BT * NH];
__device__ float d_Beta[BT * NH];
__device__ float d_O[(size_t)BT * VD];

// bf16 split operand buffers
__device__ __nv_bfloat16 d_Hh[(size_t)BT * HID];
__device__ __nv_bfloat16 d_Hl[(size_t)BT * HID];
__device__ __nv_bfloat16 d_Wbh[(size_t)HID * PST];   // [Wq|Wk|Wv|Wg] hi
__device__ __nv_bfloat16 d_Wbl[(size_t)HID * PST];   // lo
__device__ __nv_bfloat16 d_Woh[(size_t)VD * HID];
__device__ __nv_bfloat16 d_Wol[(size_t)VD * HID];
__device__ __nv_bfloat16 d_Gh[(size_t)BT * VD];
__device__ __nv_bfloat16 d_Gl[(size_t)BT * VD];

// ---------------- packed f32x2 helpers (recurrence) ----------------
__device__ __forceinline__ ull fma2(ull a, ull b, ull c) {
    ull d;
    asm("fma.rn.f32x2 %0, %1, %2, %3;" : "=l"(d) : "l"(a), "l"(b), "l"(c));
    return d;
}
__device__ __forceinline__ ull mul2(ull a, ull b) {
    ull d;
    asm("mul.rn.f32x2 %0, %1, %2;" : "=l"(d) : "l"(a), "l"(b));
    return d;
}
__device__ __forceinline__ ull add2(ull a, ull b) {
    ull d;
    asm("add.rn.f32x2 %0, %1, %2;" : "=l"(d) : "l"(a), "l"(b));
    return d;
}
__device__ __forceinline__ ull pack2(float lo, float hi) {
    ull d;
    asm("mov.b64 %0, {%1, %2};" : "=l"(d) : "f"(lo), "f"(hi));
    return d;
}
__device__ __forceinline__ void unpack2(ull v, float& lo, float& hi) {
    asm("mov.b64 {%0, %1}, %2;" : "=f"(lo), "=f"(hi) : "l"(v));
}
__device__ __forceinline__ float sigm(float x) { return 1.0f / (1.0f + __expf(-x)); }

// ---------------- mma.sync bf16 GEMM machinery ----------------
__device__ __forceinline__ uint32_t smem_u32(const void* p) {
    uint32_t a;
    asm("{ .reg .u64 t; cvta.to.shared.u64 t, %1; cvt.u32.u64 %0, t; }" : "=r"(a) : "l"(p));
    return a;
}
__device__ __forceinline__ uint32_t pkbf(float x, float y) {
    uint32_t r;
    asm("cvt.rn.bf16x2.f32 %0, %1, %2;" : "=r"(r) : "f"(y), "f"(x));
    return r;
}
__device__ __forceinline__ void ldsm_x4(uint32_t* r, uint32_t a) {
    asm volatile("ldmatrix.sync.aligned.m8n8.x4.shared.b16 {%0,%1,%2,%3}, [%4];"
                 : "=r"(r[0]), "=r"(r[1]), "=r"(r[2]), "=r"(r[3]) : "r"(a));
}
__device__ __forceinline__ void ldsm_x4_t(uint32_t* r, uint32_t a) {
    asm volatile("ldmatrix.sync.aligned.m8n8.x4.trans.shared.b16 {%0,%1,%2,%3}, [%4];"
                 : "=r"(r[0]), "=r"(r[1]), "=r"(r[2]), "=r"(r[3]) : "r"(a));
}
__device__ __forceinline__ void mma_bf16(float* d, const uint32_t* a, const uint32_t* b) {
    asm volatile(
        "mma.sync.aligned.m16n8k16.row.col.f32.bf16.bf16.f32 "
        "{%0,%1,%2,%3}, {%4,%5,%6,%7}, {%8,%9}, {%0,%1,%2,%3};"
        : "+f"(d[0]), "+f"(d[1]), "+f"(d[2]), "+f"(d[3])
        : "r"(a[0]), "r"(a[1]), "r"(a[2]), "r"(a[3]), "r"(b[0]), "r"(b[1]));
}
__device__ __forceinline__ void cpa16(uint32_t dst, const void* src) {
    asm volatile("cp.async.cg.shared.global [%0], [%1], 16;" :: "r"(dst), "l"(src));
}
__device__ __forceinline__ void cpa4(uint32_t dst, const void* src) {
    asm volatile("cp.async.ca.shared.global [%0], [%1], 4;" :: "r"(dst), "l"(src));
}
#define CP_COMMIT() asm volatile("cp.async.commit_group;" ::: "memory")
#define CP_WAIT1()  asm volatile("cp.async.wait_group 1;" ::: "memory")
#define CP_WAIT2()  asm volatile("cp.async.wait_group 2;" ::: "memory")

// tiles: 128(M) x 64(N), BK=32, 3 stages, 2 CTAs/SM
#define BM 128
#define BN 64
#define BKf 32
#define STAGES 3
#define A_STR 80
#define B_STR 144
#define AT_BYTES (128 * A_STR)
#define BTI_BYTES (32 * B_STR)
#define OFF_AH 0
#define OFF_AL AT_BYTES
#define OFF_BH (2 * AT_BYTES)
#define OFF_BL (2 * AT_BYTES + BTI_BYTES)
#define STAGE_BYTES (2 * AT_BYTES + 2 * BTI_BYTES)
#define SMEM_GB (STAGES * STAGE_BYTES)

__device__ __forceinline__ void g_issue(uint32_t st,
                                        const __nv_bfloat16* __restrict__ Ah,
                                        const __nv_bfloat16* __restrict__ Al,
                                        const __nv_bfloat16* __restrict__ Bh,
                                        const __nv_bfloat16* __restrict__ Bl,
                                        int m0, int n0, int kt, int K, int N, int tid) {
#pragma unroll
    for (int half = 0; half < 2; half++) {
        int r = (tid >> 2) + half * 64;
        int ke = (tid & 3) * 8;
        const size_t ga = (size_t)(m0 + r) * K + kt * BKf + ke;
        uint32_t so = st + r * A_STR + ke * 2;
        cpa16(so + OFF_AH, Ah + ga);
        cpa16(so + OFF_AL, Al + ga);
    }
    {
        int r = tid >> 3;
        int ke = (tid & 7) * 8;
        const size_t gb = (size_t)(kt * BKf + r) * N + n0 + ke;
        uint32_t so = st + r * B_STR + ke * 2;
        cpa16(so + OFF_BH, Bh + gb);
        cpa16(so + OFF_BL, Bl + gb);
    }
}

__device__ __forceinline__ void g_compute(uint32_t st, int wid, int lane, float (*acc)[4][4]) {
    const int wm = (wid & 3) * 32, wn = (wid >> 2) * 32;
    const int arow = lane & 15;
    const int acg = (lane >> 4) * 8;
    const int brow = (lane & 7) + ((lane >> 3) & 1) * 8;
    const int bcg = (lane >> 4) * 8;
#pragma unroll
    for (int ks = 0; ks < BKf; ks += 16) {
        uint32_t ah[2][4], al[2][4], bh[2][4], bl[2][4];
#pragma unroll
        for (int mt = 0; mt < 2; mt++) {
            uint32_t ad = st + OFF_AH + (wm + mt * 16 + arow) * A_STR + (ks + acg) * 2;
            ldsm_x4(ah[mt], ad);
            ldsm_x4(al[mt], ad + (OFF_AL - OFF_AH));
        }
#pragma unroll
        for (int nt = 0; nt < 2; nt++) {
            uint32_t bd = st + OFF_BH + (ks + brow) * B_STR + (wn + nt * 16 + bcg) * 2;
            ldsm_x4_t(bh[nt], bd);
            ldsm_x4_t(bl[nt], bd + (OFF_BL - OFF_BH));
        }
#pragma unroll
        for (int mt = 0; mt < 2; mt++)
#pragma unroll
            for (int j = 0; j < 4; j++)
                mma_bf16(acc[mt][j], ah[mt], &bh[j >> 1][(j & 1) * 2]);
#pragma unroll
        for (int mt = 0; mt < 2; mt++)
#pragma unroll
            for (int j = 0; j < 4; j++)
                mma_bf16(acc[mt][j], ah[mt], &bl[j >> 1][(j & 1) * 2]);
#pragma unroll
        for (int mt = 0; mt < 2; mt++)
#pragma unroll
            for (int j = 0; j < 4; j++)
                mma_bf16(acc[mt][j], al[mt], &bh[j >> 1][(j & 1) * 2]);
    }
}

// C[M,N] = A[M,K] @ B[K,N]; operands pre-split hi/lo bf16, fp32 out
__global__ __launch_bounds__(256, 2) void gemm_bf(const __nv_bfloat16* __restrict__ Ah,
                                                  const __nv_bfloat16* __restrict__ Al,
                                                  const __nv_bfloat16* __restrict__ Bh,
                                                  const __nv_bfloat16* __restrict__ Bl,
                                                  float* __restrict__ C,
                                                  int M, int N, int K) {
    extern __shared__ char smem[];
    const uint32_t sb = smem_u32(smem);
    const int tid = threadIdx.x, lane = tid & 31, wid = tid >> 5;
    const int m0 = blockIdx.y * BM, n0 = blockIdx.x * BN;
    const int NT = K / BKf;

    float acc[2][4][4];
#pragma unroll
    for (int mt = 0; mt < 2; mt++)
#pragma unroll
        for (int j = 0; j < 4; j++)
#pragma unroll
            for (int p = 0; p < 4; p++) acc[mt][j][p] = 0.0f;

    g_issue(sb, Ah, Al, Bh, Bl, m0, n0, 0, K, N, tid);
    CP_COMMIT();
    g_issue(sb + STAGE_BYTES, Ah, Al, Bh, Bl, m0, n0, 1, K, N, tid);
    CP_COMMIT();

    for (int kt = 0; kt < NT; kt++) {
        CP_WAIT1();
        __syncthreads();
        const int pf = kt + 2;
        if (pf < NT)
            g_issue(sb + (pf % STAGES) * STAGE_BYTES, Ah, Al, Bh, Bl, m0, n0, pf, K, N, tid);
        CP_COMMIT();
        g_compute(sb + (kt % STAGES) * STAGE_BYTES, wid, lane, acc);
    }

    const int wm = (wid & 3) * 32, wn = (wid >> 2) * 32;
    const int g = lane >> 2, t = lane & 3;
#pragma unroll
    for (int mt = 0; mt < 2; mt++)
#pragma unroll
        for (int j = 0; j < 4; j++) {
            float* p = C + (size_t)(m0 + wm + mt * 16 + g) * N + n0 + wn + j * 8 + t * 2;
            float2 c0 = make_float2(acc[mt][j][0], acc[mt][j][1]);
            float2 c1 = make_float2(acc[mt][j][2], acc[mt][j][3]);
            *(float2*)p = c0;
            *(float2*)(p + (size_t)8 * N) = c1;
        }
}

// ---------------- hi/lo bf16 split (contiguous) ----------------
__global__ __launch_bounds__(256) void split_kernel(const float4* __restrict__ src,
                                                    uint2* __restrict__ h,
                                                    uint2* __restrict__ l, int n4) {
    int i = blockIdx.x * 256 + threadIdx.x;
    if (i >= n4) return;
    float4 v = src[i];
    uint32_t h01 = pkbf(v.x, v.y), h23 = pkbf(v.z, v.w);
    float hx = __uint_as_float(h01 << 16);
    float hy = __uint_as_float(h01 & 0xffff0000u);
    float hz = __uint_as_float(h23 << 16);
    float hw = __uint_as_float(h23 & 0xffff0000u);
    h[i] = make_uint2(h01, h23);
    l[i] = make_uint2(pkbf(v.x - hx, v.y - hy), pkbf(v.z - hz, v.w - hw));
}

// ---------------- hi/lo bf16 split into strided (concatenated) dest ----------------
__global__ __launch_bounds__(256) void splitWs_kernel(const float4* __restrict__ src,
                                                      __nv_bfloat16* __restrict__ dh,
                                                      __nv_bfloat16* __restrict__ dl,
                                                      int n4, int ncols4, int colOff) {
    int i = blockIdx.x * 256 + threadIdx.x;
    if (i >= n4) return;
    int row = i / ncols4;
    int c4 = i - row * ncols4;
    float4 v = src[i];
    uint32_t h01 = pkbf(v.x, v.y), h23 = pkbf(v.z, v.w);
    float hx = __uint_as_float(h01 << 16);
    float hy = __uint_as_float(h01 & 0xffff0000u);
    float hz = __uint_as_float(h23 << 16);
    float hw = __uint_as_float(h23 & 0xffff0000u);
    size_t o = (size_t)row * PST + colOff + c4 * 4;
    *(uint2*)(dh + o) = make_uint2(h01, h23);
    *(uint2*)(dl + o) = make_uint2(pkbf(v.x - hx, v.y - hy), pkbf(v.z - hz, v.w - hw));
}

// ---------------- gate projections: g -> exp(g), beta ----------------
__global__ __launch_bounds__(256) void gate_kernel(const float* __restrict__ H,
                                                   const float* __restrict__ Wa,
                                                   const float* __restrict__ Wb,
                                                   const float* __restrict__ A_log,
                                                   const float* __restrict__ dt_bias) {
    __shared__ float hrow[HID];
    const int bt = blockIdx.x;
    const int tid = threadIdx.x;
    for (int i = tid; i < HID; i += 256) hrow[i] = H[(size_t)bt * HID + i];
    __syncthreads();
    const int w = tid >> 5, lane = tid & 31;
    for (int d = w; d < 12; d += 8) {
        const int head = d % 6;
        const float* Wc = (d < 6) ? Wa : Wb;
        float s = 0.0f;
        for (int i = lane; i < HID; i += 32) s += hrow[i] * Wc[i * NH + head];
#pragma unroll
        for (int m = 16; m > 0; m >>= 1) s += __shfl_xor_sync(0xffffffffu, s, m);
        if (lane == 0) {
            if (d < 6) {
                float x = s + dt_bias[head];
                float sp = (x > 20.0f) ? x : log1pf(expf(x));
                float g = -expf(A_log[head]) * sp;
                d_EG[bt * NH + head] = expf(g);
            } else {
                d_Beta[bt * NH + head] = sigm(s);
            }
        }
    }
}

// ---------------- causal depthwise conv + silu + per-head l2norm (q/k) ----------------
__global__ __launch_bounds__(256) void convqk_kernel(const float* __restrict__ P,
                                                     const float* __restrict__ W,
                                                     float* __restrict__ out,
                                                     float scale, int colOff) {
    const int bt = blockIdx.x;
    const int h = blockIdx.y;
    const int c = threadIdx.x;
    const int ch = h * DK + c;
    const int t = bt & (T_ - 1);
    float acc = 0.0f;
#pragma unroll
    for (int j = 0; j < CK; j++) {
        int tt = t - (CK - 1) + j;
        if (tt >= 0) acc += P[(size_t)(bt - (CK - 1) + j) * PST + colOff + ch] * W[ch * CK + j];
    }
    float y = acc * sigm(acc);  // silu

    __shared__ float red[8];
    float ss = y * y;
#pragma unroll
    for (int m = 16; m > 0; m >>= 1) ss += __shfl_xor_sync(0xffffffffu, ss, m);
    if ((c & 31) == 0) red[c >> 5] = ss;
    __syncthreads();
    float tot = 0.0f;
#pragma unroll
    for (int i = 0; i < 8; i++) tot += red[i];
    float r = rsqrtf(tot + 1e-6f);
    out[(size_t)bt * KD + ch] = y * r * scale;
}

// ---------------- causal depthwise conv + silu (v) ----------------
__global__ __launch_bounds__(256) void convv_kernel(const float* __restrict__ P,
                                                    const float* __restrict__ W) {
    const int bt = blockIdx.x;
    const int ch = blockIdx.y * 256 + threadIdx.x;
    const int t = bt & (T_ - 1);
    float acc = 0.0f;
#pragma unroll
    for (int j = 0; j < CK; j++) {
        int tt = t - (CK - 1) + j;
        if (tt >= 0) acc += P[(size_t)(bt - (CK - 1) + j) * PST + VOFF + ch] * W[ch * CK + j];
    }
    d_Vc[(size_t)bt * VD + ch] = acc * sigm(acc);
}

// ---------------- gated delta-rule recurrence (cp.async smem ring) ----------------
// 96 CTAs: (b,h) x 8 chunks of 64 cols. warp owns 8 cols; lane=(rg,cg):
// rg 0..15 -> 16 rows; cg 0..1 -> 4 cols. Ring: 4 slots of {k256,q256,v64,eg,beta}.
#define RSLOT 640   // floats per slot (2560B)
__global__ __launch_bounds__(256, 1) void recur_kernel() {
    __shared__ __align__(16) float ring[4][RSLOT];
    const int bid = blockIdx.x;
    const int chunk = bid & 7;
    const int bh = bid >> 3;
    const int b = bh / NH, h = bh % NH;
    const int tid = threadIdx.x;
    const int warp = tid >> 5, lane = tid & 31;
    const int rg = lane >> 1, cg = lane & 1;
    const int bt0 = b * T_;

    const float* Kb = d_Kc + h * DK;
    const float* Qb = d_Qc + h * DK;
    const float* Vb = d_Vc + h * DV + chunk * 64;
    float* Ob = d_O + h * DV + chunk * 64 + warp * 8 + cg * 4;

    ull S[16][2];
#pragma unroll
    for (int r = 0; r < 16; r++) { S[r][0] = 0ull; S[r][1] = 0ull; }

    // producer: each thread issues <=1 cp.async per timestep
    auto issue = [&](int slot, int t) {
        const int bt = bt0 + t;
        uint32_t sd = smem_u32(&ring[slot][0]);
        if (tid < 64) {
            cpa16(sd + tid * 16, Kb + (size_t)bt * KD + tid * 4);
        } else if (tid < 128) {
            cpa16(sd + 1024 + (tid - 64) * 16, Qb + (size_t)bt * KD + (tid - 64) * 4);
        } else if (tid < 144) {
            cpa16(sd + 2048 + (tid - 128) * 16, Vb + (size_t)bt * VD + (tid - 128) * 4);
        } else if (tid == 144) {
            cpa4(sd + 2304, d_EG + bt * NH + h);
        } else if (tid == 145) {
            cpa4(sd + 2308, d_Beta + bt * NH + h);
        }
    };

    // prime slots 0..2
#pragma unroll
    for (int p = 0; p < 3; p++) { issue(p, p); CP_COMMIT(); }

    for (int t = 0; t < T_; t++) {
        CP_WAIT2();
        __syncthreads();
        if (t + 3 < T_) issue((t + 3) & 3, t + 3);
        CP_COMMIT();

        const float* sl = ring[t & 3];
        float kf[16], qf[16];
#pragma unroll
        for (int j = 0; j < 4; j++) {
            float4 a = *(const float4*)(sl + rg * 16 + j * 4);
            kf[4 * j] = a.x; kf[4 * j + 1] = a.y; kf[4 * j + 2] = a.z; kf[4 * j + 3] = a.w;
            float4 qd = *(const float4*)(sl + 256 + rg * 16 + j * 4);
            qf[4 * j] = qd.x; qf[4 * j + 1] = qd.y; qf[4 * j + 2] = qd.z; qf[4 * j + 3] = qd.w;
        }
        float4 vv = *(const float4*)(sl + 512 + warp * 8 + cg * 4);
        const float eg = sl[576];
        const float bet = sl[577];

        // phase 1: kv = k . S (pre-decay)
        ull kv2a = 0ull, kv2b = 0ull;
#pragma unroll
        for (int r = 0; r < 16; r++) {
            ull k2 = pack2(kf[r], kf[r]);
            kv2a = fma2(k2, S[r][0], kv2a);
            kv2b = fma2(k2, S[r][1], kv2b);
        }
#pragma unroll
        for (int mask = 2; mask <= 16; mask <<= 1) {
            kv2a = add2(kv2a, __shfl_xor_sync(0xffffffffu, kv2a, mask));
            kv2b = add2(kv2b, __shfl_xor_sync(0xffffffffu, kv2b, mask));
        }
        float kv0, kv1, kv2f, kv3;
        unpack2(kv2a, kv0, kv1);
        unpack2(kv2b, kv2f, kv3);

        ull u2a = pack2((vv.x - eg * kv0) * bet, (vv.y - eg * kv1) * bet);
        ull u2b = pack2((vv.z - eg * kv2f) * bet, (vv.w - eg * kv3) * bet);
        const ull eg2 = pack2(eg, eg);

        // phase 2: S = eg*S + k (x) u ; o = q . S
        ull o2a = 0ull, o2b = 0ull;
#pragma unroll
        for (int r = 0; r < 16; r++) {
            ull k2 = pack2(kf[r], kf[r]);
            ull q2 = pack2(qf[r], qf[r]);
            S[r][0] = fma2(eg2, S[r][0], mul2(k2, u2a));
            o2a = fma2(q2, S[r][0], o2a);
            S[r][1] = fma2(eg2, S[r][1], mul2(k2, u2b));
            o2b = fma2(q2, S[r][1], o2b);
        }
#pragma unroll
        for (int mask = 2; mask <= 16; mask <<= 1) {
            o2a = add2(o2a, __shfl_xor_sync(0xffffffffu, o2a, mask));
            o2b = add2(o2b, __shfl_xor_sync(0xffffffffu, o2b, mask));
        }
        if (rg == 0) {
            float4 o4;
            unpack2(o2a, o4.x, o4.y);
            unpack2(o2b, o4.z, o4.w);
            *(float4*)(Ob + (size_t)(bt0 + t) * VD) = o4;
        }
    }
}

// ---------------- gated RMSNorm + bf16 hi/lo split (fused) ----------------
__global__ __launch_bounds__(256) void normgate_kernel(const float* __restrict__ w) {
    const int bt = blockIdx.x;
    const int h = blockIdx.y;
    const int tid = threadIdx.x;
    const size_t obase = (size_t)bt * VD + h * DV;
    const size_t gbase = (size_t)bt * PST + GOFF + h * DV;
    float o0 = d_O[obase + tid];
    float o1 = d_O[obase + tid + 256];
    float ss = o0 * o0 + o1 * o1;
    __shared__ float red[8];
#pragma unroll
    for (int m = 16; m > 0; m >>= 1) ss += __shfl_xor_sync(0xffffffffu, ss, m);
    if ((tid & 31) == 0) red[tid >> 5] = ss;
    __syncthreads();
    float tot = 0.0f;
#pragma unroll
    for (int i = 0; i < 8; i++) tot += red[i];
    float rms = rsqrtf(tot * (1.0f / (float)DV) + 1e-5f);
    float g0 = d_P[gbase + tid];
    float g1 = d_P[gbase + tid + 256];
    float r0 = o0 * rms * w[tid]       * g0 * sigm(g0);
    float r1 = o1 * rms * w[tid + 256] * g1 * sigm(g1);
    // fused bf16 hi/lo split
    uint32_t hp = pkbf(r0, r1);
    float h0 = __uint_as_float(hp << 16);
    float h1 = __uint_as_float(hp & 0xffff0000u);
    uint32_t lp = pkbf(r0 - h0, r1 - h1);
    d_Gh[obase + tid]       = __ushort_as_bfloat16((unsigned short)(hp & 0xffff));
    d_Gh[obase + tid + 256] = __ushort_as_bfloat16((unsigned short)(hp >> 16));
    d_Gl[obase + tid]       = __ushort_as_bfloat16((unsigned short)(lp & 0xffff));
    d_Gl[obase + tid + 256] = __ushort_as_bfloat16((unsigned short)(lp >> 16));
}

// ---------------- streams/events (created once at static init) ----------------
struct GdnStreams {
    cudaStream_t s1, s2;
    cudaEvent_t evRoot, evW1, evW2, evWo, evGB, evP, evK, evV;
    GdnStreams() {
        cudaStreamCreateWithFlags(&s1, cudaStreamNonBlocking);
        cudaStreamCreateWithFlags(&s2, cudaStreamNonBlocking);
        cudaEventCreateWithFlags(&evRoot, cudaEventDisableTiming);
        cudaEventCreateWithFlags(&evW1, cudaEventDisableTiming);
        cudaEventCreateWithFlags(&evW2, cudaEventDisableTiming);
        cudaEventCreateWithFlags(&evWo, cudaEventDisableTiming);
        cudaEventCreateWithFlags(&evGB, cudaEventDisableTiming);
        cudaEventCreateWithFlags(&evP, cudaEventDisableTiming);
        cudaEventCreateWithFlags(&evK, cudaEventDisableTiming);
        cudaEventCreateWithFlags(&evV, cudaEventDisableTiming);
    }
};
static GdnStreams g_s;

// ---------------- host launcher ----------------
extern "C" void kernel_launch(void* const* d_in, const int* in_sizes, int n_in,
                              void* d_out, int out_size) {
    const float* H       = (const float*)d_in[0];
    const float* Wq      = (const float*)d_in[1];
    const float* Wk      = (const float*)d_in[2];
    const float* Wv      = (const float*)d_in[3];
    const float* Wa      = (const float*)d_in[4];
    const float* Wb      = (const float*)d_in[5];
    const float* Wg      = (const float*)d_in[6];
    const float* Wo      = (const float*)d_in[7];
    const float* conv_q  = (const float*)d_in[8];
    const float* conv_k  = (const float*)d_in[9];
    const float* conv_v  = (const float*)d_in[10];
    const float* A_log   = (const float*)d_in[11];
    const float* dt_bias = (const float*)d_in[12];
    const float* onw     = (const float*)d_in[13];

    float *pp, *qc, *kc;
    cudaGetSymbolAddress((void**)&pp, d_P);
    cudaGetSymbolAddress((void**)&qc, d_Qc);
    cudaGetSymbolAddress((void**)&kc, d_Kc);

    __nv_bfloat16 *hh, *hl, *wbh, *wbl, *woh, *wol, *gh, *gl;
    cudaGetSymbolAddress((void**)&hh, d_Hh);   cudaGetSymbolAddress((void**)&hl, d_Hl);
    cudaGetSymbolAddress((void**)&wbh, d_Wbh); cudaGetSymbolAddress((void**)&wbl, d_Wbl);
    cudaGetSymbolAddress((void**)&woh, d_Woh); cudaGetSymbolAddress((void**)&wol, d_Wol);
    cudaGetSymbolAddress((void**)&gh, d_Gh);   cudaGetSymbolAddress((void**)&gl, d_Gl);

    cudaFuncSetAttribute(gemm_bf, cudaFuncAttributeMaxDynamicSharedMemorySize, SMEM_GB);

    cudaStream_t s0 = 0;
    cudaStream_t s1 = g_s.s1, s2 = g_s.s2;

    // ---- fork: root event on origin stream so side streams join the capture ----
    cudaEventRecord(g_s.evRoot, s0);
    cudaStreamWaitEvent(s1, g_s.evRoot, 0);
    cudaStreamWaitEvent(s2, g_s.evRoot, 0);

    // s0: split H
    {
        int n4 = (BT * HID) / 4;
        split_kernel<<<(n4 + 255) / 256, 256, 0, s0>>>((const float4*)H, (uint2*)hh, (uint2*)hl, n4);
    }
    // s1: Wq/Wk/Wv splits into concatenated buffer
    {
        int n4q = (HID * KD) / 4;
        splitWs_kernel<<<(n4q + 255) / 256, 256, 0, s1>>>((const float4*)Wq, wbh, wbl, n4q, KD / 4, QOFF);
        splitWs_kernel<<<(n4q + 255) / 256, 256, 0, s1>>>((const float4*)Wk, wbh, wbl, n4q, KD / 4, KOFF);
        int n4v = (HID * VD) / 4;
        splitWs_kernel<<<(n4v + 255) / 256, 256, 0, s1>>>((const float4*)Wv, wbh, wbl, n4v, VD / 4, VOFF);
        cudaEventRecord(g_s.evW1, s1);
    }
    // s2: Wg split + Wo split + gate projections
    {
        int n4v = (HID * VD) / 4;
        splitWs_kernel<<<(n4v + 255) / 256, 256, 0, s2>>>((const float4*)Wg, wbh, wbl, n4v, VD / 4, GOFF);
        cudaEventRecord(g_s.evW2, s2);
        int n4o = (VD * HID) / 4;
        split_kernel<<<(n4o + 255) / 256, 256, 0, s2>>>((const float4*)Wo, (uint2*)woh, (uint2*)wol, n4o);
        cudaEventRecord(g_s.evWo, s2);
        gate_kernel<<<BT, 256, 0, s2>>>(H, Wa, Wb, A_log, dt_bias);
        cudaEventRecord(g_s.evGB, s2);
    }

    // ---- ONE fused projection GEMM: [4096 x 9216] ----
    cudaStreamWaitEvent(s0, g_s.evW1, 0);
    cudaStreamWaitEvent(s0, g_s.evW2, 0);
    gemm_bf<<<dim3(PST / BN, BT / BM), 256, SMEM_GB, s0>>>(hh, hl, wbh, wbl, pp, BT, PST, HID);
    cudaEventRecord(g_s.evP, s0);

    // ---- convs (3-way concurrent) ----
    convqk_kernel<<<dim3(BT, NH), 256, 0, s0>>>(pp, conv_q, qc, 0.0625f, QOFF);
    cudaStreamWaitEvent(s1, g_s.evP, 0);
    convqk_kernel<<<dim3(BT, NH), 256, 0, s1>>>(pp, conv_k, kc, 1.0f, KOFF);
    cudaEventRecord(g_s.evK, s1);
    cudaStreamWaitEvent(s2, g_s.evP, 0);
    convv_kernel<<<dim3(BT, VD / 256), 256, 0, s2>>>(pp, conv_v);
    cudaEventRecord(g_s.evV, s2);

    // ---- recurrence ----
    cudaStreamWaitEvent(s0, g_s.evK, 0);
    cudaStreamWaitEvent(s0, g_s.evV, 0);
    cudaStreamWaitEvent(s0, g_s.evGB, 0);
    recur_kernel<<<96, 256, 0, s0>>>();

    // ---- epilogue: fused normgate+split, then Wo GEMM ----
    normgate_kernel<<<dim3(BT, NH), 256, 0, s0>>>(onw);
    cudaStreamWaitEvent(s0, g_s.evWo, 0);
    gemm_bf<<<dim3(HID / BN, BT / BM), 256, SMEM_GB, s0>>>(gh, gl, woh, wol, (float*)d_out, BT, HID, VD);
}

// round 15
// speedup vs baseline: 1.2798x; 1.0257x over previous
#include <cuda_runtime.h>
#include <cuda_bf16.h>
#include <cstdint>

// ---------------- problem dims ----------------
#define B_   2
#define T_   2048
#define HID  2048
#define NH   6
#define DK   256
#define DV   512
#define KD   1536      // NH*DK
#define VD   3072      // NH*DV
#define BT   4096      // B_*T_
#define CK   4

// fused projection layout: [q(1536) | k(1536) | v(3072) | g(3072)]
#define PST  9216
#define QOFF 0
#define KOFF 1536
#define VOFF 3072
#define GOFF 6144

typedef unsigned long long ull;

// ---------------- scratch (device globals; no allocs allowed) ----------------
__device__ float d_P[(size_t)BT * PST];       // fused projection output (fp32)
__device__ float d_Qc[BT * KD];
__device__ float d_Kc[BT * KD];
__device__ float d_Vc[(size_t)BT * VD];
__device__ float d_EG[BT * NH];
__device__ float d_Beta[BT * NH];
__device__ float d_O[(size_t)BT * VD];

// bf16 split operand buffers
__device__ __nv_bfloat16 d_Hh[(size_t)BT * HID];
__device__ __nv_bfloat16 d_Hl[(size_t)BT * HID];
__device__ __nv_bfloat16 d_Wbh[(size_t)HID * PST];   // [Wq|Wk|Wv|Wg] hi
__device__ __nv_bfloat16 d_Wbl[(size_t)HID * PST];   // lo
__device__ __nv_bfloat16 d_Woh[(size_t)VD * HID];
__device__ __nv_bfloat16 d_Wol[(size_t)VD * HID];
__device__ __nv_bfloat16 d_Gh[(size_t)BT * VD];
__device__ __nv_bfloat16 d_Gl[(size_t)BT * VD];

// ---------------- packed f32x2 helpers (recurrence) ----------------
__device__ __forceinline__ ull fma2(ull a, ull b, ull c) {
    ull d;
    asm("fma.rn.f32x2 %0, %1, %2, %3;" : "=l"(d) : "l"(a), "l"(b), "l"(c));
    return d;
}
__device__ __forceinline__ ull mul2(ull a, ull b) {
    ull d;
    asm("mul.rn.f32x2 %0, %1, %2;" : "=l"(d) : "l"(a), "l"(b));
    return d;
}
__device__ __forceinline__ ull add2(ull a, ull b) {
    ull d;
    asm("add.rn.f32x2 %0, %1, %2;" : "=l"(d) : "l"(a), "l"(b));
    return d;
}
__device__ __forceinline__ ull pack2(float lo, float hi) {
    ull d;
    asm("mov.b64 %0, {%1, %2};" : "=l"(d) : "f"(lo), "f"(hi));
    return d;
}
__device__ __forceinline__ void unpack2(ull v, float& lo, float& hi) {
    asm("mov.b64 {%0, %1}, %2;" : "=f"(lo), "=f"(hi) : "l"(v));
}
__device__ __forceinline__ float sigm(float x) { return 1.0f / (1.0f + __expf(-x)); }

// ---------------- mma.sync bf16 GEMM machinery ----------------
__device__ __forceinline__ uint32_t smem_u32(const void* p) {
    uint32_t a;
    asm("{ .reg .u64 t; cvta.to.shared.u64 t, %1; cvt.u32.u64 %0, t; }" : "=r"(a) : "l"(p));
    return a;
}
__device__ __forceinline__ uint32_t pkbf(float x, float y) {
    uint32_t r;
    asm("cvt.rn.bf16x2.f32 %0, %1, %2;" : "=r"(r) : "f"(y), "f"(x));
    return r;
}
__device__ __forceinline__ void ldsm_x4(uint32_t* r, uint32_t a) {
    asm volatile("ldmatrix.sync.aligned.m8n8.x4.shared.b16 {%0,%1,%2,%3}, [%4];"
                 : "=r"(r[0]), "=r"(r[1]), "=r"(r[2]), "=r"(r[3]) : "r"(a));
}
__device__ __forceinline__ void ldsm_x4_t(uint32_t* r, uint32_t a) {
    asm volatile("ldmatrix.sync.aligned.m8n8.x4.trans.shared.b16 {%0,%1,%2,%3}, [%4];"
                 : "=r"(r[0]), "=r"(r[1]), "=r"(r[2]), "=r"(r[3]) : "r"(a));
}
__device__ __forceinline__ void mma_bf16(float* d, const uint32_t* a, const uint32_t* b) {
    asm volatile(
        "mma.sync.aligned.m16n8k16.row.col.f32.bf16.bf16.f32 "
        "{%0,%1,%2,%3}, {%4,%5,%6,%7}, {%8,%9}, {%0,%1,%2,%3};"
        : "+f"(d[0]), "+f"(d[1]), "+f"(d[2]), "+f"(d[3])
        : "r"(a[0]), "r"(a[1]), "r"(a[2]), "r"(a[3]), "r"(b[0]), "r"(b[1]));
}
__device__ __forceinline__ void cpa16(uint32_t dst, const void* src) {
    asm volatile("cp.async.cg.shared.global [%0], [%1], 16;" :: "r"(dst), "l"(src));
}
__device__ __forceinline__ void cpa4(uint32_t dst, const void* src) {
    asm volatile("cp.async.ca.shared.global [%0], [%1], 4;" :: "r"(dst), "l"(src));
}
#define CP_COMMIT() asm volatile("cp.async.commit_group;" ::: "memory")
#define CP_WAIT1()  asm volatile("cp.async.wait_group 1;" ::: "memory")
#define CP_WAIT3()  asm volatile("cp.async.wait_group 3;" ::: "memory")

// tiles: 128(M) x 64(N), BK=32, 3 stages, 2 CTAs/SM
#define BM 128
#define BN 64
#define BKf 32
#define STAGES 3
#define A_STR 80
#define B_STR 144
#define AT_BYTES (128 * A_STR)
#define BTI_BYTES (32 * B_STR)
#define OFF_AH 0
#define OFF_AL AT_BYTES
#define OFF_BH (2 * AT_BYTES)
#define OFF_BL (2 * AT_BYTES + BTI_BYTES)
#define STAGE_BYTES (2 * AT_BYTES + 2 * BTI_BYTES)
#define SMEM_GB (STAGES * STAGE_BYTES)

__device__ __forceinline__ void g_issue(uint32_t st,
                                        const __nv_bfloat16* __restrict__ Ah,
                                        const __nv_bfloat16* __restrict__ Al,
                                        const __nv_bfloat16* __restrict__ Bh,
                                        const __nv_bfloat16* __restrict__ Bl,
                                        int m0, int n0, int kt, int K, int N, int tid) {
#pragma unroll
    for (int half = 0; half < 2; half++) {
        int r = (tid >> 2) + half * 64;
        int ke = (tid & 3) * 8;
        const size_t ga = (size_t)(m0 + r) * K + kt * BKf + ke;
        uint32_t so = st + r * A_STR + ke * 2;
        cpa16(so + OFF_AH, Ah + ga);
        cpa16(so + OFF_AL, Al + ga);
    }
    {
        int r = tid >> 3;
        int ke = (tid & 7) * 8;
        const size_t gb = (size_t)(kt * BKf + r) * N + n0 + ke;
        uint32_t so = st + r * B_STR + ke * 2;
        cpa16(so + OFF_BH, Bh + gb);
        cpa16(so + OFF_BL, Bl + gb);
    }
}

__device__ __forceinline__ void g_compute(uint32_t st, int wid, int lane, float (*acc)[4][4]) {
    const int wm = (wid & 3) * 32, wn = (wid >> 2) * 32;
    const int arow = lane & 15;
    const int acg = (lane >> 4) * 8;
    const int brow = (lane & 7) + ((lane >> 3) & 1) * 8;
    const int bcg = (lane >> 4) * 8;
#pragma unroll
    for (int ks = 0; ks < BKf; ks += 16) {
        uint32_t ah[2][4], al[2][4], bh[2][4], bl[2][4];
#pragma unroll
        for (int mt = 0; mt < 2; mt++) {
            uint32_t ad = st + OFF_AH + (wm + mt * 16 + arow) * A_STR + (ks + acg) * 2;
            ldsm_x4(ah[mt], ad);
            ldsm_x4(al[mt], ad + (OFF_AL - OFF_AH));
        }
#pragma unroll
        for (int nt = 0; nt < 2; nt++) {
            uint32_t bd = st + OFF_BH + (ks + brow) * B_STR + (wn + nt * 16 + bcg) * 2;
            ldsm_x4_t(bh[nt], bd);
            ldsm_x4_t(bl[nt], bd + (OFF_BL - OFF_BH));
        }
#pragma unroll
        for (int mt = 0; mt < 2; mt++)
#pragma unroll
            for (int j = 0; j < 4; j++)
                mma_bf16(acc[mt][j], ah[mt], &bh[j >> 1][(j & 1) * 2]);
#pragma unroll
        for (int mt = 0; mt < 2; mt++)
#pragma unroll
            for (int j = 0; j < 4; j++)
                mma_bf16(acc[mt][j], ah[mt], &bl[j >> 1][(j & 1) * 2]);
#pragma unroll
        for (int mt = 0; mt < 2; mt++)
#pragma unroll
            for (int j = 0; j < 4; j++)
                mma_bf16(acc[mt][j], al[mt], &bh[j >> 1][(j & 1) * 2]);
    }
}

// C[M,N] = A[M,K] @ B[K,N]; operands pre-split hi/lo bf16, fp32 out
__global__ __launch_bounds__(256, 2) void gemm_bf(const __nv_bfloat16* __restrict__ Ah,
                                                  const __nv_bfloat16* __restrict__ Al,
                                                  const __nv_bfloat16* __restrict__ Bh,
                                                  const __nv_bfloat16* __restrict__ Bl,
                                                  float* __restrict__ C,
                                                  int M, int N, int K) {
    extern __shared__ char smem[];
    const uint32_t sb = smem_u32(smem);
    const int tid = threadIdx.x, lane = tid & 31, wid = tid >> 5;
    const int m0 = blockIdx.y * BM, n0 = blockIdx.x * BN;
    const int NT = K / BKf;

    float acc[2][4][4];
#pragma unroll
    for (int mt = 0; mt < 2; mt++)
#pragma unroll
        for (int j = 0; j < 4; j++)
#pragma unroll
            for (int p = 0; p < 4; p++) acc[mt][j][p] = 0.0f;

    g_issue(sb, Ah, Al, Bh, Bl, m0, n0, 0, K, N, tid);
    CP_COMMIT();
    g_issue(sb + STAGE_BYTES, Ah, Al, Bh, Bl, m0, n0, 1, K, N, tid);
    CP_COMMIT();

    for (int kt = 0; kt < NT; kt++) {
        CP_WAIT1();
        __syncthreads();
        const int pf = kt + 2;
        if (pf < NT)
            g_issue(sb + (pf % STAGES) * STAGE_BYTES, Ah, Al, Bh, Bl, m0, n0, pf, K, N, tid);
        CP_COMMIT();
        g_compute(sb + (kt % STAGES) * STAGE_BYTES, wid, lane, acc);
    }

    const int wm = (wid & 3) * 32, wn = (wid >> 2) * 32;
    const int g = lane >> 2, t = lane & 3;
#pragma unroll
    for (int mt = 0; mt < 2; mt++)
#pragma unroll
        for (int j = 0; j < 4; j++) {
            float* p = C + (size_t)(m0 + wm + mt * 16 + g) * N + n0 + wn + j * 8 + t * 2;
            float2 c0 = make_float2(acc[mt][j][0], acc[mt][j][1]);
            float2 c1 = make_float2(acc[mt][j][2], acc[mt][j][3]);
            *(float2*)p = c0;
            *(float2*)(p + (size_t)8 * N) = c1;
        }
}

// ---------------- hi/lo bf16 split (contiguous) ----------------
__global__ __launch_bounds__(256) void split_kernel(const float4* __restrict__ src,
                                                    uint2* __restrict__ h,
                                                    uint2* __restrict__ l, int n4) {
    int i = blockIdx.x * 256 + threadIdx.x;
    if (i >= n4) return;
    float4 v = src[i];
    uint32_t h01 = pkbf(v.x, v.y), h23 = pkbf(v.z, v.w);
    float hx = __uint_as_float(h01 << 16);
    float hy = __uint_as_float(h01 & 0xffff0000u);
    float hz = __uint_as_float(h23 << 16);
    float hw = __uint_as_float(h23 & 0xffff0000u);
    h[i] = make_uint2(h01, h23);
    l[i] = make_uint2(pkbf(v.x - hx, v.y - hy), pkbf(v.z - hz, v.w - hw));
}

// ---------------- hi/lo bf16 split into strided (concatenated) dest ----------------
__global__ __launch_bounds__(256) void splitWs_kernel(const float4* __restrict__ src,
                                                      __nv_bfloat16* __restrict__ dh,
                                                      __nv_bfloat16* __restrict__ dl,
                                                      int n4, int ncols4, int colOff) {
    int i = blockIdx.x * 256 + threadIdx.x;
    if (i >= n4) return;
    int row = i / ncols4;
    int c4 = i - row * ncols4;
    float4 v = src[i];
    uint32_t h01 = pkbf(v.x, v.y), h23 = pkbf(v.z, v.w);
    float hx = __uint_as_float(h01 << 16);
    float hy = __uint_as_float(h01 & 0xffff0000u);
    float hz = __uint_as_float(h23 << 16);
    float hw = __uint_as_float(h23 & 0xffff0000u);
    size_t o = (size_t)row * PST + colOff + c4 * 4;
    *(uint2*)(dh + o) = make_uint2(h01, h23);
    *(uint2*)(dl + o) = make_uint2(pkbf(v.x - hx, v.y - hy), pkbf(v.z - hz, v.w - hw));
}

// ---------------- gate projections: g -> exp(g), beta ----------------
__global__ __launch_bounds__(256) void gate_kernel(const float* __restrict__ H,
                                                   const float* __restrict__ Wa,
                                                   const float* __restrict__ Wb,
                                                   const float* __restrict__ A_log,
                                                   const float* __restrict__ dt_bias) {
    __shared__ float hrow[HID];
    const int bt = blockIdx.x;
    const int tid = threadIdx.x;
    for (int i = tid; i < HID; i += 256) hrow[i] = H[(size_t)bt * HID + i];
    __syncthreads();
    const int w = tid >> 5, lane = tid & 31;
    for (int d = w; d < 12; d += 8) {
        const int head = d % 6;
        const float* Wc = (d < 6) ? Wa : Wb;
        float s = 0.0f;
        for (int i = lane; i < HID; i += 32) s += hrow[i] * Wc[i * NH + head];
#pragma unroll
        for (int m = 16; m > 0; m >>= 1) s += __shfl_xor_sync(0xffffffffu, s, m);
        if (lane == 0) {
            if (d < 6) {
                float x = s + dt_bias[head];
                float sp = (x > 20.0f) ? x : log1pf(expf(x));
                float g = -expf(A_log[head]) * sp;
                d_EG[bt * NH + head] = expf(g);
            } else {
                d_Beta[bt * NH + head] = sigm(s);
            }
        }
    }
}

// ---------------- causal depthwise conv + silu + per-head l2norm (q/k) ----------------
__global__ __launch_bounds__(256) void convqk_kernel(const float* __restrict__ P,
                                                     const float* __restrict__ W,
                                                     float* __restrict__ out,
                                                     float scale, int colOff) {
    const int bt = blockIdx.x;
    const int h = blockIdx.y;
    const int c = threadIdx.x;
    const int ch = h * DK + c;
    const int t = bt & (T_ - 1);
    float acc = 0.0f;
#pragma unroll
    for (int j = 0; j < CK; j++) {
        int tt = t - (CK - 1) + j;
        if (tt >= 0) acc += P[(size_t)(bt - (CK - 1) + j) * PST + colOff + ch] * W[ch * CK + j];
    }
    float y = acc * sigm(acc);  // silu

    __shared__ float red[8];
    float ss = y * y;
#pragma unroll
    for (int m = 16; m > 0; m >>= 1) ss += __shfl_xor_sync(0xffffffffu, ss, m);
    if ((c & 31) == 0) red[c >> 5] = ss;
    __syncthreads();
    float tot = 0.0f;
#pragma unroll
    for (int i = 0; i < 8; i++) tot += red[i];
    float r = rsqrtf(tot + 1e-6f);
    out[(size_t)bt * KD + ch] = y * r * scale;
}

// ---------------- causal depthwise conv + silu (v) ----------------
__global__ __launch_bounds__(256) void convv_kernel(const float* __restrict__ P,
                                                    const float* __restrict__ W) {
    const int bt = blockIdx.x;
    const int ch = blockIdx.y * 256 + threadIdx.x;
    const int t = bt & (T_ - 1);
    float acc = 0.0f;
#pragma unroll
    for (int j = 0; j < CK; j++) {
        int tt = t - (CK - 1) + j;
        if (tt >= 0) acc += P[(size_t)(bt - (CK - 1) + j) * PST + VOFF + ch] * W[ch * CK + j];
    }
    d_Vc[(size_t)bt * VD + ch] = acc * sigm(acc);
}

// ---------------- gated delta-rule recurrence (cp.async smem ring, 8 slots) ----------------
// 96 CTAs: (b,h) x 8 chunks of 64 cols. warp owns 8 cols; lane=(rg,cg):
// rg 0..15 -> 16 rows; cg 0..1 -> 4 cols. Ring: 8 slots of {k256,q256,v64,eg,beta};
// prefetch distance 5, ONE barrier per 2 timesteps (reads t,t+1 vs writes t+5,t+6
// are disjoint mod 8; wait_group 3 leaves data t and t+1 complete).
#define RSLOT 640   // floats per slot (2560B)
__global__ __launch_bounds__(256, 1) void recur_kernel() {
    __shared__ __align__(16) float ring[8][RSLOT];
    const int bid = blockIdx.x;
    const int chunk = bid & 7;
    const int bh = bid >> 3;
    const int b = bh / NH, h = bh % NH;
    const int tid = threadIdx.x;
    const int warp = tid >> 5, lane = tid & 31;
    const int rg = lane >> 1, cg = lane & 1;
    const int bt0 = b * T_;

    const float* Kb = d_Kc + h * DK;
    const float* Qb = d_Qc + h * DK;
    const float* Vb = d_Vc + h * DV + chunk * 64;
    float* Ob = d_O + h * DV + chunk * 64 + warp * 8 + cg * 4;

    ull S[16][2];
#pragma unroll
    for (int r = 0; r < 16; r++) { S[r][0] = 0ull; S[r][1] = 0ull; }

    // producer: each thread issues <=1 cp.async per timestep
    auto issue = [&](int slot, int t) {
        const int bt = bt0 + t;
        uint32_t sd = smem_u32(&ring[slot][0]);
        if (tid < 64) {
            cpa16(sd + tid * 16, Kb + (size_t)bt * KD + tid * 4);
        } else if (tid < 128) {
            cpa16(sd + 1024 + (tid - 64) * 16, Qb + (size_t)bt * KD + (tid - 64) * 4);
        } else if (tid < 144) {
            cpa16(sd + 2048 + (tid - 128) * 16, Vb + (size_t)bt * VD + (tid - 128) * 4);
        } else if (tid == 144) {
            cpa4(sd + 2304, d_EG + bt * NH + h);
        } else if (tid == 145) {
            cpa4(sd + 2308, d_Beta + bt * NH + h);
        }
    };

    // consumer body for one timestep (data must be visible in ring[t&7])
    auto step = [&](int t) {
        const float* sl = ring[t & 7];
        float kf[16], qf[16];
#pragma unroll
        for (int j = 0; j < 4; j++) {
            float4 a = *(const float4*)(sl + rg * 16 + j * 4);
            kf[4 * j] = a.x; kf[4 * j + 1] = a.y; kf[4 * j + 2] = a.z; kf[4 * j + 3] = a.w;
            float4 qd = *(const float4*)(sl + 256 + rg * 16 + j * 4);
            qf[4 * j] = qd.x; qf[4 * j + 1] = qd.y; qf[4 * j + 2] = qd.z; qf[4 * j + 3] = qd.w;
        }
        float4 vv = *(const float4*)(sl + 512 + warp * 8 + cg * 4);
        const float eg = sl[576];
        const float bet = sl[577];

        // phase 1: kv = k . S (pre-decay)
        ull kv2a = 0ull, kv2b = 0ull;
#pragma unroll
        for (int r = 0; r < 16; r++) {
            ull k2 = pack2(kf[r], kf[r]);
            kv2a = fma2(k2, S[r][0], kv2a);
            kv2b = fma2(k2, S[r][1], kv2b);
        }
#pragma unroll
        for (int mask = 2; mask <= 16; mask <<= 1) {
            kv2a = add2(kv2a, __shfl_xor_sync(0xffffffffu, kv2a, mask));
            kv2b = add2(kv2b, __shfl_xor_sync(0xffffffffu, kv2b, mask));
        }
        float kv0, kv1, kv2f, kv3;
        unpack2(kv2a, kv0, kv1);
        unpack2(kv2b, kv2f, kv3);

        ull u2a = pack2((vv.x - eg * kv0) * bet, (vv.y - eg * kv1) * bet);
        ull u2b = pack2((vv.z - eg * kv2f) * bet, (vv.w - eg * kv3) * bet);
        const ull eg2 = pack2(eg, eg);

        // phase 2: S = eg*S + k (x) u ; o = q . S
        ull o2a = 0ull, o2b = 0ull;
#pragma unroll
        for (int r = 0; r < 16; r++) {
            ull k2 = pack2(kf[r], kf[r]);
            ull q2 = pack2(qf[r], qf[r]);
            S[r][0] = fma2(eg2, S[r][0], mul2(k2, u2a));
            o2a = fma2(q2, S[r][0], o2a);
            S[r][1] = fma2(eg2, S[r][1], mul2(k2, u2b));
            o2b = fma2(q2, S[r][1], o2b);
        }
#pragma unroll
        for (int mask = 2; mask <= 16; mask <<= 1) {
            o2a = add2(o2a, __shfl_xor_sync(0xffffffffu, o2a, mask));
            o2b = add2(o2b, __shfl_xor_sync(0xffffffffu, o2b, mask));
        }
        if (rg == 0) {
            float4 o4;
            unpack2(o2a, o4.x, o4.y);
            unpack2(o2b, o4.z, o4.w);
            *(float4*)(Ob + (size_t)(bt0 + t) * VD) = o4;
        }
    };

    // prime slots 0..4 (groups carry data 0..4, one commit each)
#pragma unroll
    for (int p = 0; p < 5; p++) { issue(p, p); CP_COMMIT(); }

    for (int t = 0; t < T_; t += 2) {
        CP_WAIT3();           // data t and t+1 complete (<=3 newer groups outstanding)
        __syncthreads();      // all warps past reads of slots (t+5)&7,(t+6)&7 from 8 ago

        if (t + 5 < T_) issue((t + 5) & 7, t + 5);
        CP_COMMIT();
        step(t);

        if (t + 6 < T_) issue((t + 6) & 7, t + 6);
        CP_COMMIT();
        step(t + 1);
    }
}

// ---------------- gated RMSNorm + bf16 hi/lo split (fused) ----------------
__global__ __launch_bounds__(256) void normgate_kernel(const float* __restrict__ w) {
    const int bt = blockIdx.x;
    const int h = blockIdx.y;
    const int tid = threadIdx.x;
    const size_t obase = (size_t)bt * VD + h * DV;
    const size_t gbase = (size_t)bt * PST + GOFF + h * DV;
    float o0 = d_O[obase + tid];
    float o1 = d_O[obase + tid + 256];
    float ss = o0 * o0 + o1 * o1;
    __shared__ float red[8];
#pragma unroll
    for (int m = 16; m > 0; m >>= 1) ss += __shfl_xor_sync(0xffffffffu, ss, m);
    if ((tid & 31) == 0) red[tid >> 5] = ss;
    __syncthreads();
    float tot = 0.0f;
#pragma unroll
    for (int i = 0; i < 8; i++) tot += red[i];
    float rms = rsqrtf(tot * (1.0f / (float)DV) + 1e-5f);
    float g0 = d_P[gbase + tid];
    float g1 = d_P[gbase + tid + 256];
    float r0 = o0 * rms * w[tid]       * g0 * sigm(g0);
    float r1 = o1 * rms * w[tid + 256] * g1 * sigm(g1);
    // fused bf16 hi/lo split
    uint32_t hp = pkbf(r0, r1);
    float h0 = __uint_as_float(hp << 16);
    float h1 = __uint_as_float(hp & 0xffff0000u);
    uint32_t lp = pkbf(r0 - h0, r1 - h1);
    d_Gh[obase + tid]       = __ushort_as_bfloat16((unsigned short)(hp & 0xffff));
    d_Gh[obase + tid + 256] = __ushort_as_bfloat16((unsigned short)(hp >> 16));
    d_Gl[obase + tid]       = __ushort_as_bfloat16((unsigned short)(lp & 0xffff));
    d_Gl[obase + tid + 256] = __ushort_as_bfloat16((unsigned short)(lp >> 16));
}

// ---------------- streams/events (created once at static init) ----------------
struct GdnStreams {
    cudaStream_t s1, s2;
    cudaEvent_t evRoot, evW1, evW2, evWo, evGB, evP, evK, evV;
    GdnStreams() {
        cudaStreamCreateWithFlags(&s1, cudaStreamNonBlocking);
        cudaStreamCreateWithFlags(&s2, cudaStreamNonBlocking);
        cudaEventCreateWithFlags(&evRoot, cudaEventDisableTiming);
        cudaEventCreateWithFlags(&evW1, cudaEventDisableTiming);
        cudaEventCreateWithFlags(&evW2, cudaEventDisableTiming);
        cudaEventCreateWithFlags(&evWo, cudaEventDisableTiming);
        cudaEventCreateWithFlags(&evGB, cudaEventDisableTiming);
        cudaEventCreateWithFlags(&evP, cudaEventDisableTiming);
        cudaEventCreateWithFlags(&evK, cudaEventDisableTiming);
        cudaEventCreateWithFlags(&evV, cudaEventDisableTiming);
    }
};
static GdnStreams g_s;

// ---------------- host launcher ----------------
extern "C" void kernel_launch(void* const* d_in, const int* in_sizes, int n_in,
                              void* d_out, int out_size) {
    const float* H       = (const float*)d_in[0];
    const float* Wq      = (const float*)d_in[1];
    const float* Wk      = (const float*)d_in[2];
    const float* Wv      = (const float*)d_in[3];
    const float* Wa      = (const float*)d_in[4];
    const float* Wb      = (const float*)d_in[5];
    const float* Wg      = (const float*)d_in[6];
    const float* Wo      = (const float*)d_in[7];
    const float* conv_q  = (const float*)d_in[8];
    const float* conv_k  = (const float*)d_in[9];
    const float* conv_v  = (const float*)d_in[10];
    const float* A_log   = (const float*)d_in[11];
    const float* dt_bias = (const float*)d_in[12];
    const float* onw     = (const float*)d_in[13];

    float *pp, *qc, *kc;
    cudaGetSymbolAddress((void**)&pp, d_P);
    cudaGetSymbolAddress((void**)&qc, d_Qc);
    cudaGetSymbolAddress((void**)&kc, d_Kc);

    __nv_bfloat16 *hh, *hl, *wbh, *wbl, *woh, *wol, *gh, *gl;
    cudaGetSymbolAddress((void**)&hh, d_Hh);   cudaGetSymbolAddress((void**)&hl, d_Hl);
    cudaGetSymbolAddress((void**)&wbh, d_Wbh); cudaGetSymbolAddress((void**)&wbl, d_Wbl);
    cudaGetSymbolAddress((void**)&woh, d_Woh); cudaGetSymbolAddress((void**)&wol, d_Wol);
    cudaGetSymbolAddress((void**)&gh, d_Gh);   cudaGetSymbolAddress((void**)&gl, d_Gl);

    cudaFuncSetAttribute(gemm_bf, cudaFuncAttributeMaxDynamicSharedMemorySize, SMEM_GB);

    cudaStream_t s0 = 0;
    cudaStream_t s1 = g_s.s1, s2 = g_s.s2;

    // ---- fork: root event on origin stream so side streams join the capture ----
    cudaEventRecord(g_s.evRoot, s0);
    cudaStreamWaitEvent(s1, g_s.evRoot, 0);
    cudaStreamWaitEvent(s2, g_s.evRoot, 0);

    // s0: split H
    {
        int n4 = (BT * HID) / 4;
        split_kernel<<<(n4 + 255) / 256, 256, 0, s0>>>((const float4*)H, (uint2*)hh, (uint2*)hl, n4);
    }
    // s1: Wq/Wk/Wv splits into concatenated buffer
    {
        int n4q = (HID * KD) / 4;
        splitWs_kernel<<<(n4q + 255) / 256, 256, 0, s1>>>((const float4*)Wq, wbh, wbl, n4q, KD / 4, QOFF);
        splitWs_kernel<<<(n4q + 255) / 256, 256, 0, s1>>>((const float4*)Wk, wbh, wbl, n4q, KD / 4, KOFF);
        int n4v = (HID * VD) / 4;
        splitWs_kernel<<<(n4v + 255) / 256, 256, 0, s1>>>((const float4*)Wv, wbh, wbl, n4v, VD / 4, VOFF);
        cudaEventRecord(g_s.evW1, s1);
    }
    // s2: Wg split + Wo split + gate projections
    {
        int n4v = (HID * VD) / 4;
        splitWs_kernel<<<(n4v + 255) / 256, 256, 0, s2>>>((const float4*)Wg, wbh, wbl, n4v, VD / 4, GOFF);
        cudaEventRecord(g_s.evW2, s2);
        int n4o = (VD * HID) / 4;
        split_kernel<<<(n4o + 255) / 256, 256, 0, s2>>>((const float4*)Wo, (uint2*)woh, (uint2*)wol, n4o);
        cudaEventRecord(g_s.evWo, s2);
        gate_kernel<<<BT, 256, 0, s2>>>(H, Wa, Wb, A_log, dt_bias);
        cudaEventRecord(g_s.evGB, s2);
    }

    // ---- ONE fused projection GEMM: [4096 x 9216] ----
    cudaStreamWaitEvent(s0, g_s.evW1, 0);
    cudaStreamWaitEvent(s0, g_s.evW2, 0);
    gemm_bf<<<dim3(PST / BN, BT / BM), 256, SMEM_GB, s0>>>(hh, hl, wbh, wbl, pp, BT, PST, HID);
    cudaEventRecord(g_s.evP, s0);

    // ---- convs (3-way concurrent) ----
    convqk_kernel<<<dim3(BT, NH), 256, 0, s0>>>(pp, conv_q, qc, 0.0625f, QOFF);
    cudaStreamWaitEvent(s1, g_s.evP, 0);
    convqk_kernel<<<dim3(BT, NH), 256, 0, s1>>>(pp, conv_k, kc, 1.0f, KOFF);
    cudaEventRecord(g_s.evK, s1);
    cudaStreamWaitEvent(s2, g_s.evP, 0);
    convv_kernel<<<dim3(BT, VD / 256), 256, 0, s2>>>(pp, conv_v);
    cudaEventRecord(g_s.evV, s2);

    // ---- recurrence ----
    cudaStreamWaitEvent(s0, g_s.evK, 0);
    cudaStreamWaitEvent(s0, g_s.evV, 0);
    cudaStreamWaitEvent(s0, g_s.evGB, 0);
    recur_kernel<<<96, 256, 0, s0>>>();

    // ---- epilogue: fused normgate+split, then Wo GEMM ----
    normgate_kernel<<<dim3(BT, NH), 256, 0, s0>>>(onw);
    cudaStreamWaitEvent(s0, g_s.evWo, 0);
    gemm_bf<<<dim3(HID / BN, BT / BM), 256, SMEM_GB, s0>>>(gh, gl, woh, wol, (float*)d_out, BT, HID, VD);
}